// round 3
// baseline (speedup 1.0000x reference)
#include <cuda_runtime.h>
#include <math.h>

#define BB 2
#define TT 4096
#define EE 512
#define HH 8
#define DD 64
#define CHUNK 128
#define NCH (TT/CHUNK)     // 32
#define NBH (BB*HH)        // 16
#define EPSF 1e-6f

#define MROWS (BB*TT)      // 8192

// ---------------- scratch (__device__ globals; no allocation allowed) ----------
__device__ float g_q[MROWS*EE];
__device__ float g_k[MROWS*EE];
__device__ float g_v[MROWS*EE];
__device__ float g_attn[MROWS*EE];
__device__ float g_Mc[NBH*NCH*DD*DD];
__device__ float g_zc[NBH*NCH*DD];
__device__ float g_Mp[NBH*NCH*DD*DD];
__device__ float g_zp[NBH*NCH*DD];

// ---------------- GEMM: Y[m][n] = sum_k A[m][k]*W[n][k] + bias[n], opt elu+1 ---
// M=8192, N=512, K=512. BM=BN=128, BK=16, 256 threads, 8x8 register tile.
template<int ACT>
__global__ __launch_bounds__(256) void gemm_kernel(
    const float* __restrict__ A, const float* __restrict__ W,
    const float* __restrict__ bias, float* __restrict__ Y)
{
    const int K = EE, N = EE;
    __shared__ __align__(16) float As[16][132];
    __shared__ __align__(16) float Ws[16][132];

    int m0 = blockIdx.x * 128;
    int n0 = blockIdx.y * 128;
    int tid = threadIdx.x;
    int tx = tid & 15, ty = tid >> 4;

    float acc[8][8];
#pragma unroll
    for (int i = 0; i < 8; i++)
#pragma unroll
        for (int j = 0; j < 8; j++) acc[i][j] = 0.f;

    for (int k0 = 0; k0 < K; k0 += 16) {
        // load tiles (transposed into smem): 512 float4 each for A and W
#pragma unroll
        for (int p = 0; p < 2; p++) {
            int idx = tid + p * 256;         // 0..511
            int row = idx >> 2;              // 0..127
            int c4  = (idx & 3) * 4;         // 0,4,8,12
            float4 a = *(const float4*)&A[(size_t)(m0 + row) * K + k0 + c4];
            As[c4 + 0][row] = a.x; As[c4 + 1][row] = a.y;
            As[c4 + 2][row] = a.z; As[c4 + 3][row] = a.w;
            float4 w = *(const float4*)&W[(size_t)(n0 + row) * K + k0 + c4];
            Ws[c4 + 0][row] = w.x; Ws[c4 + 1][row] = w.y;
            Ws[c4 + 2][row] = w.z; Ws[c4 + 3][row] = w.w;
        }
        __syncthreads();

#pragma unroll
        for (int kk = 0; kk < 16; kk++) {
            float4 a0 = *(const float4*)&As[kk][ty * 8];
            float4 a1 = *(const float4*)&As[kk][ty * 8 + 4];
            float4 b0 = *(const float4*)&Ws[kk][tx * 8];
            float4 b1 = *(const float4*)&Ws[kk][tx * 8 + 4];
            float ra[8] = {a0.x, a0.y, a0.z, a0.w, a1.x, a1.y, a1.z, a1.w};
            float rb[8] = {b0.x, b0.y, b0.z, b0.w, b1.x, b1.y, b1.z, b1.w};
#pragma unroll
            for (int i = 0; i < 8; i++)
#pragma unroll
                for (int j = 0; j < 8; j++) acc[i][j] += ra[i] * rb[j];
        }
        __syncthreads();
    }

#pragma unroll
    for (int i = 0; i < 8; i++) {
        int m = m0 + ty * 8 + i;
#pragma unroll
        for (int j = 0; j < 8; j++) {
            int n = n0 + tx * 8 + j;
            float yv = acc[i][j] + bias[n];
            if (ACT) yv = (yv > 0.f) ? (yv + 1.f) : expf(yv);
            Y[(size_t)m * N + n] = yv;
        }
    }
}

// ---------------- Pass A: per-chunk KV outer sums + key sums -------------------
__global__ __launch_bounds__(256) void chunk_sums_kernel()
{
    int blk = blockIdx.x;           // bh*NCH + c
    int bh = blk / NCH, c = blk % NCH;
    int b = bh / HH, h = bh % HH;

    extern __shared__ float sm[];
    float* sk = sm;                 // [128][65]
    float* sv = sm + CHUNK * 65;    // [128][65]

    int tid = threadIdx.x;
    const float* kg = g_k + ((size_t)b * TT + (size_t)c * CHUNK) * EE + h * DD;
    const float* vg = g_v + ((size_t)b * TT + (size_t)c * CHUNK) * EE + h * DD;

    for (int i = tid; i < CHUNK * 16; i += 256) {
        int t = i >> 4, d4 = (i & 15) * 4;
        float4 a = *(const float4*)&kg[(size_t)t * EE + d4];
        sk[t * 65 + d4 + 0] = a.x; sk[t * 65 + d4 + 1] = a.y;
        sk[t * 65 + d4 + 2] = a.z; sk[t * 65 + d4 + 3] = a.w;
        float4 w = *(const float4*)&vg[(size_t)t * EE + d4];
        sv[t * 65 + d4 + 0] = w.x; sv[t * 65 + d4 + 1] = w.y;
        sv[t * 65 + d4 + 2] = w.z; sv[t * 65 + d4 + 3] = w.w;
    }
    __syncthreads();

    int d = tid >> 2;
    int eg = (tid & 3) * 16;
    float acc[16];
#pragma unroll
    for (int j = 0; j < 16; j++) acc[j] = 0.f;
    float zacc = 0.f;

    for (int t = 0; t < CHUNK; t++) {
        float kv = sk[t * 65 + d];
        zacc += kv;
        const float* vr = &sv[t * 65 + eg];
#pragma unroll
        for (int j = 0; j < 16; j++) acc[j] += kv * vr[j];
    }

    float* Mout = g_Mc + (size_t)blk * DD * DD + d * DD + eg;
#pragma unroll
    for (int j = 0; j < 16; j++) Mout[j] = acc[j];
    if ((tid & 3) == 0) g_zc[(size_t)blk * DD + d] = zacc;
}

// ---------------- Pass B: exclusive prefix over chunks -------------------------
__global__ void prefix_kernel()
{
    int idx = blockIdx.x * 256 + threadIdx.x;
    const int PER = DD * DD + DD;   // 4160
    if (idx >= NBH * PER) return;
    int bh = idx / PER;
    int r  = idx % PER;
    if (r < DD * DD) {
        float run = 0.f;
        for (int c = 0; c < NCH; c++) {
            size_t o = (size_t)(bh * NCH + c) * DD * DD + r;
            g_Mp[o] = run;
            run += g_Mc[o];
        }
    } else {
        int d = r - DD * DD;
        float run = 0.f;
        for (int c = 0; c < NCH; c++) {
            size_t o = (size_t)(bh * NCH + c) * DD + d;
            g_zp[o] = run;
            run += g_zc[o];
        }
    }
}

// ---------------- Pass C: per-chunk output ------------------------------------
__global__ __launch_bounds__(256) void chunk_attn_kernel()
{
    int blk = blockIdx.x;
    int bh = blk / NCH, c = blk % NCH;
    int b = bh / HH, h = bh % HH;

    extern __shared__ float sm[];
    float* sq  = sm;                        // [128][65]
    float* sk  = sq + 128 * 65;             // [128][65]
    float* sv  = sk + 128 * 65;             // [128][65]
    float* sS  = sv + 128 * 65;             // [64][65]
    float* sz  = sS + 64 * 65;              // [64]
    float* sdi = sz + 64;                   // [128]
    float* sA  = sdi + 128;                 // [128][128]

    int tid = threadIdx.x;
    const float* qg = g_q + ((size_t)b * TT + (size_t)c * CHUNK) * EE + h * DD;
    const float* kg = g_k + ((size_t)b * TT + (size_t)c * CHUNK) * EE + h * DD;
    const float* vg = g_v + ((size_t)b * TT + (size_t)c * CHUNK) * EE + h * DD;
    const float* Mp = g_Mp + (size_t)blk * DD * DD;
    const float* zp = g_zp + (size_t)blk * DD;

    for (int i = tid; i < CHUNK * 16; i += 256) {
        int t = i >> 4, d4 = (i & 15) * 4;
        float4 a = *(const float4*)&qg[(size_t)t * EE + d4];
        sq[t * 65 + d4 + 0] = a.x; sq[t * 65 + d4 + 1] = a.y;
        sq[t * 65 + d4 + 2] = a.z; sq[t * 65 + d4 + 3] = a.w;
        float4 w = *(const float4*)&kg[(size_t)t * EE + d4];
        sk[t * 65 + d4 + 0] = w.x; sk[t * 65 + d4 + 1] = w.y;
        sk[t * 65 + d4 + 2] = w.z; sk[t * 65 + d4 + 3] = w.w;
        float4 v = *(const float4*)&vg[(size_t)t * EE + d4];
        sv[t * 65 + d4 + 0] = v.x; sv[t * 65 + d4 + 1] = v.y;
        sv[t * 65 + d4 + 2] = v.z; sv[t * 65 + d4 + 3] = v.w;
    }
    for (int i = tid; i < DD * DD; i += 256) {
        sS[(i >> 6) * 65 + (i & 63)] = Mp[i];
    }
    if (tid < DD) sz[tid] = zp[tid];
    __syncthreads();

    // A[t][s] = q_t . k_s  (s <= t)
    for (int i = tid; i < 128 * 128; i += 256) {
        int t = i >> 7, s = i & 127;
        if (s <= t) {
            const float* qr = &sq[t * 65];
            const float* kr = &sk[s * 65];
            float a = 0.f;
#pragma unroll
            for (int dd = 0; dd < DD; dd++) a += qr[dd] * kr[dd];
            sA[t * 128 + s] = a;
        }
    }
    __syncthreads();

    // denominators
    if (tid < 128) {
        int t = tid;
        const float* qr = &sq[t * 65];
        float den = EPSF;
#pragma unroll
        for (int dd = 0; dd < DD; dd++) den += qr[dd] * sz[dd];
        for (int s = 0; s <= t; s++) den += sA[t * 128 + s];
        sdi[t] = 1.f / den;
    }
    __syncthreads();

    // out[t][e] = ( q_t . S_pref[:,e] + sum_{s<=t} A[t][s] v_s[e] ) * inv_den[t]
    float* og = g_attn + ((size_t)b * TT + (size_t)c * CHUNK) * EE + h * DD;
    for (int i = tid; i < 128 * 64; i += 256) {
        int t = i >> 6, e = i & 63;
        const float* qr = &sq[t * 65];
        float acc = 0.f;
#pragma unroll
        for (int dd = 0; dd < DD; dd++) acc += qr[dd] * sS[dd * 65 + e];
        const float* ar = &sA[t * 128];
        for (int s = 0; s <= t; s++) acc += ar[s] * sv[s * 65 + e];
        og[(size_t)t * EE + e] = acc * sdi[t];
    }
}

// ---------------- host ----------------------------------------------------------
extern "C" void kernel_launch(void* const* d_in, const int* in_sizes, int n_in,
                              void* d_out, int out_size)
{
    const float* x  = (const float*)d_in[0];
    const float* Wq = (const float*)d_in[1];
    const float* bq = (const float*)d_in[2];
    const float* Wk = (const float*)d_in[3];
    const float* bk = (const float*)d_in[4];
    const float* Wv = (const float*)d_in[5];
    const float* bv = (const float*)d_in[6];
    const float* Wo = (const float*)d_in[7];
    const float* bo = (const float*)d_in[8];
    float* out = (float*)d_out;

    float *pq, *pk, *pv, *pa;
    cudaGetSymbolAddress((void**)&pq, g_q);
    cudaGetSymbolAddress((void**)&pk, g_k);
    cudaGetSymbolAddress((void**)&pv, g_v);
    cudaGetSymbolAddress((void**)&pa, g_attn);

    // set max dynamic smem (idempotent, non-capturing host calls)
    cudaFuncSetAttribute(chunk_sums_kernel,
                         cudaFuncAttributeMaxDynamicSharedMemorySize, 2 * 128 * 65 * 4);
    int smC = (3 * 128 * 65 + 64 * 65 + 64 + 128 + 128 * 128) * 4;
    cudaFuncSetAttribute(chunk_attn_kernel,
                         cudaFuncAttributeMaxDynamicSharedMemorySize, smC);

    dim3 ggrid(MROWS / 128, EE / 128);   // 64 x 4

    gemm_kernel<1><<<ggrid, 256>>>(x, Wq, bq, pq);
    gemm_kernel<1><<<ggrid, 256>>>(x, Wk, bk, pk);
    gemm_kernel<0><<<ggrid, 256>>>(x, Wv, bv, pv);

    chunk_sums_kernel<<<NBH * NCH, 256, 2 * 128 * 65 * 4>>>();

    int totalPref = NBH * (DD * DD + DD);
    prefix_kernel<<<(totalPref + 255) / 256, 256>>>();

    chunk_attn_kernel<<<NBH * NCH, 256, smC>>>();

    gemm_kernel<0><<<ggrid, 256>>>(pa, Wo, bo, out);
}

// round 4
// speedup vs baseline: 1.0051x; 1.0051x over previous
#include <cuda_runtime.h>
#include <math.h>

#define BB 2
#define TT 4096
#define EE 512
#define HH 8
#define DD 64
#define CHUNK 128
#define NCH (TT/CHUNK)     // 32
#define NBH (BB*HH)        // 16
#define EPSF 1e-6f

#define MROWS (BB*TT)      // 8192

// ---------------- scratch (__device__ globals; no allocation allowed) ----------
__device__ float g_q[MROWS*EE];
__device__ float g_k[MROWS*EE];
__device__ float g_v[MROWS*EE];
__device__ float g_attn[MROWS*EE];
__device__ float g_Mc[NBH*NCH*DD*DD];
__device__ float g_zc[NBH*NCH*DD];
__device__ float g_Mp[NBH*NCH*DD*DD];
__device__ float g_zp[NBH*NCH*DD];

// ---------------- GEMM: Y[m][n] = sum_k A[m][k]*W[n][k] + bias[n], opt elu+1 ---
// M=8192, N=512, K=512. BM=BN=128, BK=16, 256 threads, 8x8 register tile.
template<int ACT>
__global__ __launch_bounds__(256) void gemm_kernel(
    const float* __restrict__ A, const float* __restrict__ W,
    const float* __restrict__ bias, float* __restrict__ Y)
{
    const int K = EE, N = EE;
    __shared__ __align__(16) float As[16][132];
    __shared__ __align__(16) float Ws[16][132];

    int m0 = blockIdx.x * 128;
    int n0 = blockIdx.y * 128;
    int tid = threadIdx.x;
    int tx = tid & 15, ty = tid >> 4;

    float acc[8][8];
#pragma unroll
    for (int i = 0; i < 8; i++)
#pragma unroll
        for (int j = 0; j < 8; j++) acc[i][j] = 0.f;

    for (int k0 = 0; k0 < K; k0 += 16) {
        // load tiles (transposed into smem): 512 float4 each for A and W
#pragma unroll
        for (int p = 0; p < 2; p++) {
            int idx = tid + p * 256;         // 0..511
            int row = idx >> 2;              // 0..127
            int c4  = (idx & 3) * 4;         // 0,4,8,12
            float4 a = *(const float4*)&A[(size_t)(m0 + row) * K + k0 + c4];
            As[c4 + 0][row] = a.x; As[c4 + 1][row] = a.y;
            As[c4 + 2][row] = a.z; As[c4 + 3][row] = a.w;
            float4 w = *(const float4*)&W[(size_t)(n0 + row) * K + k0 + c4];
            Ws[c4 + 0][row] = w.x; Ws[c4 + 1][row] = w.y;
            Ws[c4 + 2][row] = w.z; Ws[c4 + 3][row] = w.w;
        }
        __syncthreads();

#pragma unroll
        for (int kk = 0; kk < 16; kk++) {
            float4 a0 = *(const float4*)&As[kk][ty * 8];
            float4 a1 = *(const float4*)&As[kk][ty * 8 + 4];
            float4 b0 = *(const float4*)&Ws[kk][tx * 8];
            float4 b1 = *(const float4*)&Ws[kk][tx * 8 + 4];
            float ra[8] = {a0.x, a0.y, a0.z, a0.w, a1.x, a1.y, a1.z, a1.w};
            float rb[8] = {b0.x, b0.y, b0.z, b0.w, b1.x, b1.y, b1.z, b1.w};
#pragma unroll
            for (int i = 0; i < 8; i++)
#pragma unroll
                for (int j = 0; j < 8; j++) acc[i][j] += ra[i] * rb[j];
        }
        __syncthreads();
    }

#pragma unroll
    for (int i = 0; i < 8; i++) {
        int m = m0 + ty * 8 + i;
#pragma unroll
        for (int j = 0; j < 8; j++) {
            int n = n0 + tx * 8 + j;
            float yv = acc[i][j] + bias[n];
            if (ACT) yv = (yv > 0.f) ? (yv + 1.f) : expf(yv);
            Y[(size_t)m * N + n] = yv;
        }
    }
}

// ---------------- Pass A: per-chunk KV outer sums + key sums -------------------
__global__ __launch_bounds__(256) void chunk_sums_kernel()
{
    int blk = blockIdx.x;           // bh*NCH + c
    int bh = blk / NCH, c = blk % NCH;
    int b = bh / HH, h = bh % HH;

    extern __shared__ float sm[];
    float* sk = sm;                 // [128][65]
    float* sv = sm + CHUNK * 65;    // [128][65]

    int tid = threadIdx.x;
    const float* kg = g_k + ((size_t)b * TT + (size_t)c * CHUNK) * EE + h * DD;
    const float* vg = g_v + ((size_t)b * TT + (size_t)c * CHUNK) * EE + h * DD;

    for (int i = tid; i < CHUNK * 16; i += 256) {
        int t = i >> 4, d4 = (i & 15) * 4;
        float4 a = *(const float4*)&kg[(size_t)t * EE + d4];
        sk[t * 65 + d4 + 0] = a.x; sk[t * 65 + d4 + 1] = a.y;
        sk[t * 65 + d4 + 2] = a.z; sk[t * 65 + d4 + 3] = a.w;
        float4 w = *(const float4*)&vg[(size_t)t * EE + d4];
        sv[t * 65 + d4 + 0] = w.x; sv[t * 65 + d4 + 1] = w.y;
        sv[t * 65 + d4 + 2] = w.z; sv[t * 65 + d4 + 3] = w.w;
    }
    __syncthreads();

    int d = tid >> 2;
    int eg = (tid & 3) * 16;
    float acc[16];
#pragma unroll
    for (int j = 0; j < 16; j++) acc[j] = 0.f;
    float zacc = 0.f;

    for (int t = 0; t < CHUNK; t++) {
        float kv = sk[t * 65 + d];
        zacc += kv;
        const float* vr = &sv[t * 65 + eg];
#pragma unroll
        for (int j = 0; j < 16; j++) acc[j] += kv * vr[j];
    }

    float* Mout = g_Mc + (size_t)blk * DD * DD + d * DD + eg;
#pragma unroll
    for (int j = 0; j < 16; j++) Mout[j] = acc[j];
    if ((tid & 3) == 0) g_zc[(size_t)blk * DD + d] = zacc;
}

// ---------------- Pass B: exclusive prefix over chunks -------------------------
__global__ void prefix_kernel()
{
    int idx = blockIdx.x * 256 + threadIdx.x;
    const int PER = DD * DD + DD;   // 4160
    if (idx >= NBH * PER) return;
    int bh = idx / PER;
    int r  = idx % PER;
    if (r < DD * DD) {
        float run = 0.f;
        for (int c = 0; c < NCH; c++) {
            size_t o = (size_t)(bh * NCH + c) * DD * DD + r;
            g_Mp[o] = run;
            run += g_Mc[o];
        }
    } else {
        int d = r - DD * DD;
        float run = 0.f;
        for (int c = 0; c < NCH; c++) {
            size_t o = (size_t)(bh * NCH + c) * DD + d;
            g_zp[o] = run;
            run += g_zc[o];
        }
    }
}

// ---------------- Pass C: per-chunk output ------------------------------------
__global__ __launch_bounds__(256) void chunk_attn_kernel()
{
    int blk = blockIdx.x;
    int bh = blk / NCH, c = blk % NCH;
    int b = bh / HH, h = bh % HH;

    extern __shared__ float sm[];
    float* sq  = sm;                        // [128][65]
    float* sk  = sq + 128 * 65;             // [128][65]
    float* sv  = sk + 128 * 65;             // [128][65]
    float* sS  = sv + 128 * 65;             // [64][65]
    float* sz  = sS + 64 * 65;              // [64]
    float* sdi = sz + 64;                   // [128]
    float* sA  = sdi + 128;                 // [128][128]

    int tid = threadIdx.x;
    const float* qg = g_q + ((size_t)b * TT + (size_t)c * CHUNK) * EE + h * DD;
    const float* kg = g_k + ((size_t)b * TT + (size_t)c * CHUNK) * EE + h * DD;
    const float* vg = g_v + ((size_t)b * TT + (size_t)c * CHUNK) * EE + h * DD;
    const float* Mp = g_Mp + (size_t)blk * DD * DD;
    const float* zp = g_zp + (size_t)blk * DD;

    for (int i = tid; i < CHUNK * 16; i += 256) {
        int t = i >> 4, d4 = (i & 15) * 4;
        float4 a = *(const float4*)&qg[(size_t)t * EE + d4];
        sq[t * 65 + d4 + 0] = a.x; sq[t * 65 + d4 + 1] = a.y;
        sq[t * 65 + d4 + 2] = a.z; sq[t * 65 + d4 + 3] = a.w;
        float4 w = *(const float4*)&kg[(size_t)t * EE + d4];
        sk[t * 65 + d4 + 0] = w.x; sk[t * 65 + d4 + 1] = w.y;
        sk[t * 65 + d4 + 2] = w.z; sk[t * 65 + d4 + 3] = w.w;
        float4 v = *(const float4*)&vg[(size_t)t * EE + d4];
        sv[t * 65 + d4 + 0] = v.x; sv[t * 65 + d4 + 1] = v.y;
        sv[t * 65 + d4 + 2] = v.z; sv[t * 65 + d4 + 3] = v.w;
    }
    for (int i = tid; i < DD * DD; i += 256) {
        sS[(i >> 6) * 65 + (i & 63)] = Mp[i];
    }
    if (tid < DD) sz[tid] = zp[tid];
    __syncthreads();

    // A[t][s] = q_t . k_s  (s <= t)
    for (int i = tid; i < 128 * 128; i += 256) {
        int t = i >> 7, s = i & 127;
        if (s <= t) {
            const float* qr = &sq[t * 65];
            const float* kr = &sk[s * 65];
            float a = 0.f;
#pragma unroll
            for (int dd = 0; dd < DD; dd++) a += qr[dd] * kr[dd];
            sA[t * 128 + s] = a;
        }
    }
    __syncthreads();

    // denominators
    if (tid < 128) {
        int t = tid;
        const float* qr = &sq[t * 65];
        float den = EPSF;
#pragma unroll
        for (int dd = 0; dd < DD; dd++) den += qr[dd] * sz[dd];
        for (int s = 0; s <= t; s++) den += sA[t * 128 + s];
        sdi[t] = 1.f / den;
    }
    __syncthreads();

    // out[t][e] = ( q_t . S_pref[:,e] + sum_{s<=t} A[t][s] v_s[e] ) * inv_den[t]
    float* og = g_attn + ((size_t)b * TT + (size_t)c * CHUNK) * EE + h * DD;
    for (int i = tid; i < 128 * 64; i += 256) {
        int t = i >> 6, e = i & 63;
        const float* qr = &sq[t * 65];
        float acc = 0.f;
#pragma unroll
        for (int dd = 0; dd < DD; dd++) acc += qr[dd] * sS[dd * 65 + e];
        const float* ar = &sA[t * 128];
        for (int s = 0; s <= t; s++) acc += ar[s] * sv[s * 65 + e];
        og[(size_t)t * EE + e] = acc * sdi[t];
    }
}

// ---------------- host ----------------------------------------------------------
extern "C" void kernel_launch(void* const* d_in, const int* in_sizes, int n_in,
                              void* d_out, int out_size)
{
    const float* x  = (const float*)d_in[0];
    const float* Wq = (const float*)d_in[1];
    const float* bq = (const float*)d_in[2];
    const float* Wk = (const float*)d_in[3];
    const float* bk = (const float*)d_in[4];
    const float* Wv = (const float*)d_in[5];
    const float* bv = (const float*)d_in[6];
    const float* Wo = (const float*)d_in[7];
    const float* bo = (const float*)d_in[8];
    float* out = (float*)d_out;

    float *pq, *pk, *pv, *pa;
    cudaGetSymbolAddress((void**)&pq, g_q);
    cudaGetSymbolAddress((void**)&pk, g_k);
    cudaGetSymbolAddress((void**)&pv, g_v);
    cudaGetSymbolAddress((void**)&pa, g_attn);

    // set max dynamic smem (idempotent, non-capturing host calls)
    cudaFuncSetAttribute(chunk_sums_kernel,
                         cudaFuncAttributeMaxDynamicSharedMemorySize, 2 * 128 * 65 * 4);
    int smC = (3 * 128 * 65 + 64 * 65 + 64 + 128 + 128 * 128) * 4;
    cudaFuncSetAttribute(chunk_attn_kernel,
                         cudaFuncAttributeMaxDynamicSharedMemorySize, smC);

    dim3 ggrid(MROWS / 128, EE / 128);   // 64 x 4

    gemm_kernel<1><<<ggrid, 256>>>(x, Wq, bq, pq);
    gemm_kernel<1><<<ggrid, 256>>>(x, Wk, bk, pk);
    gemm_kernel<0><<<ggrid, 256>>>(x, Wv, bv, pv);

    chunk_sums_kernel<<<NBH * NCH, 256, 2 * 128 * 65 * 4>>>();

    int totalPref = NBH * (DD * DD + DD);
    prefix_kernel<<<(totalPref + 255) / 256, 256>>>();

    chunk_attn_kernel<<<NBH * NCH, 256, smC>>>();

    gemm_kernel<0><<<ggrid, 256>>>(pa, Wo, bo, out);
}

// round 5
// speedup vs baseline: 1.0063x; 1.0012x over previous
#include <cuda_runtime.h>
#include <math.h>

#define BB 2
#define TT 4096
#define EE 512
#define HH 8
#define DD 64
#define CHUNK 128
#define NCH (TT/CHUNK)     // 32
#define NBH (BB*HH)        // 16
#define EPSF 1e-6f

#define MROWS (BB*TT)      // 8192

// ---------------- scratch (__device__ globals; no allocation allowed) ----------
__device__ float g_q[MROWS*EE];
__device__ float g_k[MROWS*EE];
__device__ float g_v[MROWS*EE];
__device__ float g_attn[MROWS*EE];
__device__ float g_Mc[NBH*NCH*DD*DD];
__device__ float g_zc[NBH*NCH*DD];
__device__ float g_Mp[NBH*NCH*DD*DD];
__device__ float g_zp[NBH*NCH*DD];

// ---------------- GEMM: Y[m][n] = sum_k A[m][k]*W[n][k] + bias[n], opt elu+1 ---
// M=8192, N=512, K=512. BM=BN=128, BK=16, 256 threads, 8x8 register tile.
template<int ACT>
__global__ __launch_bounds__(256) void gemm_kernel(
    const float* __restrict__ A, const float* __restrict__ W,
    const float* __restrict__ bias, float* __restrict__ Y)
{
    const int K = EE, N = EE;
    __shared__ __align__(16) float As[16][132];
    __shared__ __align__(16) float Ws[16][132];

    int m0 = blockIdx.x * 128;
    int n0 = blockIdx.y * 128;
    int tid = threadIdx.x;
    int tx = tid & 15, ty = tid >> 4;

    float acc[8][8];
#pragma unroll
    for (int i = 0; i < 8; i++)
#pragma unroll
        for (int j = 0; j < 8; j++) acc[i][j] = 0.f;

    for (int k0 = 0; k0 < K; k0 += 16) {
        // load tiles (transposed into smem): 512 float4 each for A and W
#pragma unroll
        for (int p = 0; p < 2; p++) {
            int idx = tid + p * 256;         // 0..511
            int row = idx >> 2;              // 0..127
            int c4  = (idx & 3) * 4;         // 0,4,8,12
            float4 a = *(const float4*)&A[(size_t)(m0 + row) * K + k0 + c4];
            As[c4 + 0][row] = a.x; As[c4 + 1][row] = a.y;
            As[c4 + 2][row] = a.z; As[c4 + 3][row] = a.w;
            float4 w = *(const float4*)&W[(size_t)(n0 + row) * K + k0 + c4];
            Ws[c4 + 0][row] = w.x; Ws[c4 + 1][row] = w.y;
            Ws[c4 + 2][row] = w.z; Ws[c4 + 3][row] = w.w;
        }
        __syncthreads();

#pragma unroll
        for (int kk = 0; kk < 16; kk++) {
            float4 a0 = *(const float4*)&As[kk][ty * 8];
            float4 a1 = *(const float4*)&As[kk][ty * 8 + 4];
            float4 b0 = *(const float4*)&Ws[kk][tx * 8];
            float4 b1 = *(const float4*)&Ws[kk][tx * 8 + 4];
            float ra[8] = {a0.x, a0.y, a0.z, a0.w, a1.x, a1.y, a1.z, a1.w};
            float rb[8] = {b0.x, b0.y, b0.z, b0.w, b1.x, b1.y, b1.z, b1.w};
#pragma unroll
            for (int i = 0; i < 8; i++)
#pragma unroll
                for (int j = 0; j < 8; j++) acc[i][j] += ra[i] * rb[j];
        }
        __syncthreads();
    }

#pragma unroll
    for (int i = 0; i < 8; i++) {
        int m = m0 + ty * 8 + i;
#pragma unroll
        for (int j = 0; j < 8; j++) {
            int n = n0 + tx * 8 + j;
            float yv = acc[i][j] + bias[n];
            if (ACT) yv = (yv > 0.f) ? (yv + 1.f) : expf(yv);
            Y[(size_t)m * N + n] = yv;
        }
    }
}

// ---------------- Pass A: per-chunk KV outer sums + key sums -------------------
__global__ __launch_bounds__(256) void chunk_sums_kernel()
{
    int blk = blockIdx.x;           // bh*NCH + c
    int bh = blk / NCH, c = blk % NCH;
    int b = bh / HH, h = bh % HH;

    extern __shared__ float sm[];
    float* sk = sm;                 // [128][65]
    float* sv = sm + CHUNK * 65;    // [128][65]

    int tid = threadIdx.x;
    const float* kg = g_k + ((size_t)b * TT + (size_t)c * CHUNK) * EE + h * DD;
    const float* vg = g_v + ((size_t)b * TT + (size_t)c * CHUNK) * EE + h * DD;

    for (int i = tid; i < CHUNK * 16; i += 256) {
        int t = i >> 4, d4 = (i & 15) * 4;
        float4 a = *(const float4*)&kg[(size_t)t * EE + d4];
        sk[t * 65 + d4 + 0] = a.x; sk[t * 65 + d4 + 1] = a.y;
        sk[t * 65 + d4 + 2] = a.z; sk[t * 65 + d4 + 3] = a.w;
        float4 w = *(const float4*)&vg[(size_t)t * EE + d4];
        sv[t * 65 + d4 + 0] = w.x; sv[t * 65 + d4 + 1] = w.y;
        sv[t * 65 + d4 + 2] = w.z; sv[t * 65 + d4 + 3] = w.w;
    }
    __syncthreads();

    int d = tid >> 2;
    int eg = (tid & 3) * 16;
    float acc[16];
#pragma unroll
    for (int j = 0; j < 16; j++) acc[j] = 0.f;
    float zacc = 0.f;

    for (int t = 0; t < CHUNK; t++) {
        float kv = sk[t * 65 + d];
        zacc += kv;
        const float* vr = &sv[t * 65 + eg];
#pragma unroll
        for (int j = 0; j < 16; j++) acc[j] += kv * vr[j];
    }

    float* Mout = g_Mc + (size_t)blk * DD * DD + d * DD + eg;
#pragma unroll
    for (int j = 0; j < 16; j++) Mout[j] = acc[j];
    if ((tid & 3) == 0) g_zc[(size_t)blk * DD + d] = zacc;
}

// ---------------- Pass B: exclusive prefix over chunks -------------------------
__global__ void prefix_kernel()
{
    int idx = blockIdx.x * 256 + threadIdx.x;
    const int PER = DD * DD + DD;   // 4160
    if (idx >= NBH * PER) return;
    int bh = idx / PER;
    int r  = idx % PER;
    if (r < DD * DD) {
        float run = 0.f;
        for (int c = 0; c < NCH; c++) {
            size_t o = (size_t)(bh * NCH + c) * DD * DD + r;
            g_Mp[o] = run;
            run += g_Mc[o];
        }
    } else {
        int d = r - DD * DD;
        float run = 0.f;
        for (int c = 0; c < NCH; c++) {
            size_t o = (size_t)(bh * NCH + c) * DD + d;
            g_zp[o] = run;
            run += g_zc[o];
        }
    }
}

// ---------------- Pass C: per-chunk output ------------------------------------
__global__ __launch_bounds__(256) void chunk_attn_kernel()
{
    int blk = blockIdx.x;
    int bh = blk / NCH, c = blk % NCH;
    int b = bh / HH, h = bh % HH;

    extern __shared__ float sm[];
    float* sq  = sm;                        // [128][65]
    float* sk  = sq + 128 * 65;             // [128][65]
    float* sv  = sk + 128 * 65;             // [128][65]
    float* sS  = sv + 128 * 65;             // [64][65]
    float* sz  = sS + 64 * 65;              // [64]
    float* sdi = sz + 64;                   // [128]
    float* sA  = sdi + 128;                 // [128][128]

    int tid = threadIdx.x;
    const float* qg = g_q + ((size_t)b * TT + (size_t)c * CHUNK) * EE + h * DD;
    const float* kg = g_k + ((size_t)b * TT + (size_t)c * CHUNK) * EE + h * DD;
    const float* vg = g_v + ((size_t)b * TT + (size_t)c * CHUNK) * EE + h * DD;
    const float* Mp = g_Mp + (size_t)blk * DD * DD;
    const float* zp = g_zp + (size_t)blk * DD;

    for (int i = tid; i < CHUNK * 16; i += 256) {
        int t = i >> 4, d4 = (i & 15) * 4;
        float4 a = *(const float4*)&qg[(size_t)t * EE + d4];
        sq[t * 65 + d4 + 0] = a.x; sq[t * 65 + d4 + 1] = a.y;
        sq[t * 65 + d4 + 2] = a.z; sq[t * 65 + d4 + 3] = a.w;
        float4 w = *(const float4*)&kg[(size_t)t * EE + d4];
        sk[t * 65 + d4 + 0] = w.x; sk[t * 65 + d4 + 1] = w.y;
        sk[t * 65 + d4 + 2] = w.z; sk[t * 65 + d4 + 3] = w.w;
        float4 v = *(const float4*)&vg[(size_t)t * EE + d4];
        sv[t * 65 + d4 + 0] = v.x; sv[t * 65 + d4 + 1] = v.y;
        sv[t * 65 + d4 + 2] = v.z; sv[t * 65 + d4 + 3] = v.w;
    }
    for (int i = tid; i < DD * DD; i += 256) {
        sS[(i >> 6) * 65 + (i & 63)] = Mp[i];
    }
    if (tid < DD) sz[tid] = zp[tid];
    __syncthreads();

    // A[t][s] = q_t . k_s  (s <= t)
    for (int i = tid; i < 128 * 128; i += 256) {
        int t = i >> 7, s = i & 127;
        if (s <= t) {
            const float* qr = &sq[t * 65];
            const float* kr = &sk[s * 65];
            float a = 0.f;
#pragma unroll
            for (int dd = 0; dd < DD; dd++) a += qr[dd] * kr[dd];
            sA[t * 128 + s] = a;
        }
    }
    __syncthreads();

    // denominators
    if (tid < 128) {
        int t = tid;
        const float* qr = &sq[t * 65];
        float den = EPSF;
#pragma unroll
        for (int dd = 0; dd < DD; dd++) den += qr[dd] * sz[dd];
        for (int s = 0; s <= t; s++) den += sA[t * 128 + s];
        sdi[t] = 1.f / den;
    }
    __syncthreads();

    // out[t][e] = ( q_t . S_pref[:,e] + sum_{s<=t} A[t][s] v_s[e] ) * inv_den[t]
    float* og = g_attn + ((size_t)b * TT + (size_t)c * CHUNK) * EE + h * DD;
    for (int i = tid; i < 128 * 64; i += 256) {
        int t = i >> 6, e = i & 63;
        const float* qr = &sq[t * 65];
        float acc = 0.f;
#pragma unroll
        for (int dd = 0; dd < DD; dd++) acc += qr[dd] * sS[dd * 65 + e];
        const float* ar = &sA[t * 128];
        for (int s = 0; s <= t; s++) acc += ar[s] * sv[s * 65 + e];
        og[(size_t)t * EE + e] = acc * sdi[t];
    }
}

// ---------------- host ----------------------------------------------------------
extern "C" void kernel_launch(void* const* d_in, const int* in_sizes, int n_in,
                              void* d_out, int out_size)
{
    const float* x  = (const float*)d_in[0];
    const float* Wq = (const float*)d_in[1];
    const float* bq = (const float*)d_in[2];
    const float* Wk = (const float*)d_in[3];
    const float* bk = (const float*)d_in[4];
    const float* Wv = (const float*)d_in[5];
    const float* bv = (const float*)d_in[6];
    const float* Wo = (const float*)d_in[7];
    const float* bo = (const float*)d_in[8];
    float* out = (float*)d_out;

    float *pq, *pk, *pv, *pa;
    cudaGetSymbolAddress((void**)&pq, g_q);
    cudaGetSymbolAddress((void**)&pk, g_k);
    cudaGetSymbolAddress((void**)&pv, g_v);
    cudaGetSymbolAddress((void**)&pa, g_attn);

    // set max dynamic smem (idempotent, non-capturing host calls)
    cudaFuncSetAttribute(chunk_sums_kernel,
                         cudaFuncAttributeMaxDynamicSharedMemorySize, 2 * 128 * 65 * 4);
    int smC = (3 * 128 * 65 + 64 * 65 + 64 + 128 + 128 * 128) * 4;
    cudaFuncSetAttribute(chunk_attn_kernel,
                         cudaFuncAttributeMaxDynamicSharedMemorySize, smC);

    dim3 ggrid(MROWS / 128, EE / 128);   // 64 x 4

    gemm_kernel<1><<<ggrid, 256>>>(x, Wq, bq, pq);
    gemm_kernel<1><<<ggrid, 256>>>(x, Wk, bk, pk);
    gemm_kernel<0><<<ggrid, 256>>>(x, Wv, bv, pv);

    chunk_sums_kernel<<<NBH * NCH, 256, 2 * 128 * 65 * 4>>>();

    int totalPref = NBH * (DD * DD + DD);
    prefix_kernel<<<(totalPref + 255) / 256, 256>>>();

    chunk_attn_kernel<<<NBH * NCH, 256, smC>>>();

    gemm_kernel<0><<<ggrid, 256>>>(pa, Wo, bo, out);
}

// round 6
// speedup vs baseline: 1.0063x; 1.0000x over previous
#include <cuda_runtime.h>
#include <math.h>

#define BB 2
#define TT 4096
#define EE 512
#define HH 8
#define DD 64
#define CHUNK 128
#define NCH (TT/CHUNK)     // 32
#define NBH (BB*HH)        // 16
#define EPSF 1e-6f

#define MROWS (BB*TT)      // 8192

// ---------------- scratch (__device__ globals; no allocation allowed) ----------
__device__ float g_q[MROWS*EE];
__device__ float g_k[MROWS*EE];
__device__ float g_v[MROWS*EE];
__device__ float g_attn[MROWS*EE];
__device__ float g_Mc[NBH*NCH*DD*DD];
__device__ float g_zc[NBH*NCH*DD];
__device__ float g_Mp[NBH*NCH*DD*DD];
__device__ float g_zp[NBH*NCH*DD];

// ---------------- GEMM: Y[m][n] = sum_k A[m][k]*W[n][k] + bias[n], opt elu+1 ---
// M=8192, N=512, K=512. BM=BN=128, BK=16, 256 threads, 8x8 register tile.
template<int ACT>
__global__ __launch_bounds__(256) void gemm_kernel(
    const float* __restrict__ A, const float* __restrict__ W,
    const float* __restrict__ bias, float* __restrict__ Y)
{
    const int K = EE, N = EE;
    __shared__ __align__(16) float As[16][132];
    __shared__ __align__(16) float Ws[16][132];

    int m0 = blockIdx.x * 128;
    int n0 = blockIdx.y * 128;
    int tid = threadIdx.x;
    int tx = tid & 15, ty = tid >> 4;

    float acc[8][8];
#pragma unroll
    for (int i = 0; i < 8; i++)
#pragma unroll
        for (int j = 0; j < 8; j++) acc[i][j] = 0.f;

    for (int k0 = 0; k0 < K; k0 += 16) {
        // load tiles (transposed into smem): 512 float4 each for A and W
#pragma unroll
        for (int p = 0; p < 2; p++) {
            int idx = tid + p * 256;         // 0..511
            int row = idx >> 2;              // 0..127
            int c4  = (idx & 3) * 4;         // 0,4,8,12
            float4 a = *(const float4*)&A[(size_t)(m0 + row) * K + k0 + c4];
            As[c4 + 0][row] = a.x; As[c4 + 1][row] = a.y;
            As[c4 + 2][row] = a.z; As[c4 + 3][row] = a.w;
            float4 w = *(const float4*)&W[(size_t)(n0 + row) * K + k0 + c4];
            Ws[c4 + 0][row] = w.x; Ws[c4 + 1][row] = w.y;
            Ws[c4 + 2][row] = w.z; Ws[c4 + 3][row] = w.w;
        }
        __syncthreads();

#pragma unroll
        for (int kk = 0; kk < 16; kk++) {
            float4 a0 = *(const float4*)&As[kk][ty * 8];
            float4 a1 = *(const float4*)&As[kk][ty * 8 + 4];
            float4 b0 = *(const float4*)&Ws[kk][tx * 8];
            float4 b1 = *(const float4*)&Ws[kk][tx * 8 + 4];
            float ra[8] = {a0.x, a0.y, a0.z, a0.w, a1.x, a1.y, a1.z, a1.w};
            float rb[8] = {b0.x, b0.y, b0.z, b0.w, b1.x, b1.y, b1.z, b1.w};
#pragma unroll
            for (int i = 0; i < 8; i++)
#pragma unroll
                for (int j = 0; j < 8; j++) acc[i][j] += ra[i] * rb[j];
        }
        __syncthreads();
    }

#pragma unroll
    for (int i = 0; i < 8; i++) {
        int m = m0 + ty * 8 + i;
#pragma unroll
        for (int j = 0; j < 8; j++) {
            int n = n0 + tx * 8 + j;
            float yv = acc[i][j] + bias[n];
            if (ACT) yv = (yv > 0.f) ? (yv + 1.f) : expf(yv);
            Y[(size_t)m * N + n] = yv;
        }
    }
}

// ---------------- Pass A: per-chunk KV outer sums + key sums -------------------
__global__ __launch_bounds__(256) void chunk_sums_kernel()
{
    int blk = blockIdx.x;           // bh*NCH + c
    int bh = blk / NCH, c = blk % NCH;
    int b = bh / HH, h = bh % HH;

    extern __shared__ float sm[];
    float* sk = sm;                 // [128][65]
    float* sv = sm + CHUNK * 65;    // [128][65]

    int tid = threadIdx.x;
    const float* kg = g_k + ((size_t)b * TT + (size_t)c * CHUNK) * EE + h * DD;
    const float* vg = g_v + ((size_t)b * TT + (size_t)c * CHUNK) * EE + h * DD;

    for (int i = tid; i < CHUNK * 16; i += 256) {
        int t = i >> 4, d4 = (i & 15) * 4;
        float4 a = *(const float4*)&kg[(size_t)t * EE + d4];
        sk[t * 65 + d4 + 0] = a.x; sk[t * 65 + d4 + 1] = a.y;
        sk[t * 65 + d4 + 2] = a.z; sk[t * 65 + d4 + 3] = a.w;
        float4 w = *(const float4*)&vg[(size_t)t * EE + d4];
        sv[t * 65 + d4 + 0] = w.x; sv[t * 65 + d4 + 1] = w.y;
        sv[t * 65 + d4 + 2] = w.z; sv[t * 65 + d4 + 3] = w.w;
    }
    __syncthreads();

    int d = tid >> 2;
    int eg = (tid & 3) * 16;
    float acc[16];
#pragma unroll
    for (int j = 0; j < 16; j++) acc[j] = 0.f;
    float zacc = 0.f;

    for (int t = 0; t < CHUNK; t++) {
        float kv = sk[t * 65 + d];
        zacc += kv;
        const float* vr = &sv[t * 65 + eg];
#pragma unroll
        for (int j = 0; j < 16; j++) acc[j] += kv * vr[j];
    }

    float* Mout = g_Mc + (size_t)blk * DD * DD + d * DD + eg;
#pragma unroll
    for (int j = 0; j < 16; j++) Mout[j] = acc[j];
    if ((tid & 3) == 0) g_zc[(size_t)blk * DD + d] = zacc;
}

// ---------------- Pass B: exclusive prefix over chunks -------------------------
__global__ void prefix_kernel()
{
    int idx = blockIdx.x * 256 + threadIdx.x;
    const int PER = DD * DD + DD;   // 4160
    if (idx >= NBH * PER) return;
    int bh = idx / PER;
    int r  = idx % PER;
    if (r < DD * DD) {
        float run = 0.f;
        for (int c = 0; c < NCH; c++) {
            size_t o = (size_t)(bh * NCH + c) * DD * DD + r;
            g_Mp[o] = run;
            run += g_Mc[o];
        }
    } else {
        int d = r - DD * DD;
        float run = 0.f;
        for (int c = 0; c < NCH; c++) {
            size_t o = (size_t)(bh * NCH + c) * DD + d;
            g_zp[o] = run;
            run += g_zc[o];
        }
    }
}

// ---------------- Pass C: per-chunk output ------------------------------------
__global__ __launch_bounds__(256) void chunk_attn_kernel()
{
    int blk = blockIdx.x;
    int bh = blk / NCH, c = blk % NCH;
    int b = bh / HH, h = bh % HH;

    extern __shared__ float sm[];
    float* sq  = sm;                        // [128][65]
    float* sk  = sq + 128 * 65;             // [128][65]
    float* sv  = sk + 128 * 65;             // [128][65]
    float* sS  = sv + 128 * 65;             // [64][65]
    float* sz  = sS + 64 * 65;              // [64]
    float* sdi = sz + 64;                   // [128]
    float* sA  = sdi + 128;                 // [128][128]

    int tid = threadIdx.x;
    const float* qg = g_q + ((size_t)b * TT + (size_t)c * CHUNK) * EE + h * DD;
    const float* kg = g_k + ((size_t)b * TT + (size_t)c * CHUNK) * EE + h * DD;
    const float* vg = g_v + ((size_t)b * TT + (size_t)c * CHUNK) * EE + h * DD;
    const float* Mp = g_Mp + (size_t)blk * DD * DD;
    const float* zp = g_zp + (size_t)blk * DD;

    for (int i = tid; i < CHUNK * 16; i += 256) {
        int t = i >> 4, d4 = (i & 15) * 4;
        float4 a = *(const float4*)&qg[(size_t)t * EE + d4];
        sq[t * 65 + d4 + 0] = a.x; sq[t * 65 + d4 + 1] = a.y;
        sq[t * 65 + d4 + 2] = a.z; sq[t * 65 + d4 + 3] = a.w;
        float4 w = *(const float4*)&kg[(size_t)t * EE + d4];
        sk[t * 65 + d4 + 0] = w.x; sk[t * 65 + d4 + 1] = w.y;
        sk[t * 65 + d4 + 2] = w.z; sk[t * 65 + d4 + 3] = w.w;
        float4 v = *(const float4*)&vg[(size_t)t * EE + d4];
        sv[t * 65 + d4 + 0] = v.x; sv[t * 65 + d4 + 1] = v.y;
        sv[t * 65 + d4 + 2] = v.z; sv[t * 65 + d4 + 3] = v.w;
    }
    for (int i = tid; i < DD * DD; i += 256) {
        sS[(i >> 6) * 65 + (i & 63)] = Mp[i];
    }
    if (tid < DD) sz[tid] = zp[tid];
    __syncthreads();

    // A[t][s] = q_t . k_s  (s <= t)
    for (int i = tid; i < 128 * 128; i += 256) {
        int t = i >> 7, s = i & 127;
        if (s <= t) {
            const float* qr = &sq[t * 65];
            const float* kr = &sk[s * 65];
            float a = 0.f;
#pragma unroll
            for (int dd = 0; dd < DD; dd++) a += qr[dd] * kr[dd];
            sA[t * 128 + s] = a;
        }
    }
    __syncthreads();

    // denominators
    if (tid < 128) {
        int t = tid;
        const float* qr = &sq[t * 65];
        float den = EPSF;
#pragma unroll
        for (int dd = 0; dd < DD; dd++) den += qr[dd] * sz[dd];
        for (int s = 0; s <= t; s++) den += sA[t * 128 + s];
        sdi[t] = 1.f / den;
    }
    __syncthreads();

    // out[t][e] = ( q_t . S_pref[:,e] + sum_{s<=t} A[t][s] v_s[e] ) * inv_den[t]
    float* og = g_attn + ((size_t)b * TT + (size_t)c * CHUNK) * EE + h * DD;
    for (int i = tid; i < 128 * 64; i += 256) {
        int t = i >> 6, e = i & 63;
        const float* qr = &sq[t * 65];
        float acc = 0.f;
#pragma unroll
        for (int dd = 0; dd < DD; dd++) acc += qr[dd] * sS[dd * 65 + e];
        const float* ar = &sA[t * 128];
        for (int s = 0; s <= t; s++) acc += ar[s] * sv[s * 65 + e];
        og[(size_t)t * EE + e] = acc * sdi[t];
    }
}

// ---------------- host ----------------------------------------------------------
extern "C" void kernel_launch(void* const* d_in, const int* in_sizes, int n_in,
                              void* d_out, int out_size)
{
    const float* x  = (const float*)d_in[0];
    const float* Wq = (const float*)d_in[1];
    const float* bq = (const float*)d_in[2];
    const float* Wk = (const float*)d_in[3];
    const float* bk = (const float*)d_in[4];
    const float* Wv = (const float*)d_in[5];
    const float* bv = (const float*)d_in[6];
    const float* Wo = (const float*)d_in[7];
    const float* bo = (const float*)d_in[8];
    float* out = (float*)d_out;

    float *pq, *pk, *pv, *pa;
    cudaGetSymbolAddress((void**)&pq, g_q);
    cudaGetSymbolAddress((void**)&pk, g_k);
    cudaGetSymbolAddress((void**)&pv, g_v);
    cudaGetSymbolAddress((void**)&pa, g_attn);

    // set max dynamic smem (idempotent, non-capturing host calls)
    cudaFuncSetAttribute(chunk_sums_kernel,
                         cudaFuncAttributeMaxDynamicSharedMemorySize, 2 * 128 * 65 * 4);
    int smC = (3 * 128 * 65 + 64 * 65 + 64 + 128 + 128 * 128) * 4;
    cudaFuncSetAttribute(chunk_attn_kernel,
                         cudaFuncAttributeMaxDynamicSharedMemorySize, smC);

    dim3 ggrid(MROWS / 128, EE / 128);   // 64 x 4

    gemm_kernel<1><<<ggrid, 256>>>(x, Wq, bq, pq);
    gemm_kernel<1><<<ggrid, 256>>>(x, Wk, bk, pk);
    gemm_kernel<0><<<ggrid, 256>>>(x, Wv, bv, pv);

    chunk_sums_kernel<<<NBH * NCH, 256, 2 * 128 * 65 * 4>>>();

    int totalPref = NBH * (DD * DD + DD);
    prefix_kernel<<<(totalPref + 255) / 256, 256>>>();

    chunk_attn_kernel<<<NBH * NCH, 256, smC>>>();

    gemm_kernel<0><<<ggrid, 256>>>(pa, Wo, bo, out);
}

// round 9
// speedup vs baseline: 1.4496x; 1.4405x over previous
#include <cuda_runtime.h>
#include <cuda_bf16.h>
#include <math.h>
#include <stdint.h>

#define BB 2
#define TT 4096
#define EE 512
#define HH 8
#define DD 64
#define CHUNK 128
#define NCH (TT/CHUNK)     // 32
#define NBH (BB*HH)        // 16
#define EPSF 1e-6f
#define MROWS (BB*TT)      // 8192

// ---------------- scratch (__device__ globals) ---------------------------------
__device__ float g_q[MROWS*EE];
__device__ float g_k[MROWS*EE];
__device__ float g_v[MROWS*EE];
__device__ float g_attn[MROWS*EE];
__device__ float g_Mc[NBH*NCH*DD*DD];
__device__ float g_zc[NBH*NCH*DD];
__device__ float g_Mp[NBH*NCH*DD*DD];
__device__ float g_zp[NBH*NCH*DD];

// bf16 hi/lo splits
__device__ __nv_bfloat16 g_xh[MROWS*EE];
__device__ __nv_bfloat16 g_xl[MROWS*EE];
__device__ __nv_bfloat16 g_ah[MROWS*EE];
__device__ __nv_bfloat16 g_al[MROWS*EE];
__device__ __nv_bfloat16 g_wh[4*EE*EE];
__device__ __nv_bfloat16 g_wl[4*EE*EE];

// ---------------- helpers -------------------------------------------------------
__device__ __forceinline__ uint32_t smem_u32(const void* p) {
    uint32_t a;
    asm("{ .reg .u64 t; cvta.to.shared.u64 t, %1; cvt.u32.u64 %0, t; }"
        : "=r"(a) : "l"(p));
    return a;
}

#define SWZ128(x) ((x) ^ (((x) >> 3) & 0x70))

__device__ __forceinline__ void ldsm_x4(uint32_t r[4], uint32_t addr) {
    asm volatile("ldmatrix.sync.aligned.m8n8.x4.shared.b16 {%0,%1,%2,%3}, [%4];"
                 : "=r"(r[0]), "=r"(r[1]), "=r"(r[2]), "=r"(r[3]) : "r"(addr));
}
// B is stored [n][k] (k-contiguous) == col-major KxN: NON-trans x2 gives the
// canonical m16n8k16 B fragment (lane l -> B[k=(l%4)*2+i][n=l/4]).
__device__ __forceinline__ void ldsm_x2(uint32_t r[2], uint32_t addr) {
    asm volatile("ldmatrix.sync.aligned.m8n8.x2.shared.b16 {%0,%1}, [%2];"
                 : "=r"(r[0]), "=r"(r[1]) : "r"(addr));
}
__device__ __forceinline__ void mma_bf16(float c[4], const uint32_t a[4], const uint32_t b[2]) {
    asm volatile(
        "mma.sync.aligned.m16n8k16.row.col.f32.bf16.bf16.f32 "
        "{%0,%1,%2,%3}, {%4,%5,%6,%7}, {%8,%9}, {%0,%1,%2,%3};"
        : "+f"(c[0]), "+f"(c[1]), "+f"(c[2]), "+f"(c[3])
        : "r"(a[0]), "r"(a[1]), "r"(a[2]), "r"(a[3]), "r"(b[0]), "r"(b[1]));
}

// ---------------- split: fp32 -> bf16 hi + bf16 lo ------------------------------
__global__ __launch_bounds__(256) void split_kernel(
    const float* __restrict__ s, __nv_bfloat16* __restrict__ h,
    __nv_bfloat16* __restrict__ l, int n4)
{
    int i = blockIdx.x * 256 + threadIdx.x;
    if (i >= n4) return;
    float4 v = ((const float4*)s)[i];
    __nv_bfloat16 hx = __float2bfloat16(v.x);
    __nv_bfloat16 hy = __float2bfloat16(v.y);
    __nv_bfloat16 hz = __float2bfloat16(v.z);
    __nv_bfloat16 hw = __float2bfloat16(v.w);
    __nv_bfloat16 lx = __float2bfloat16(v.x - __bfloat162float(hx));
    __nv_bfloat16 ly = __float2bfloat16(v.y - __bfloat162float(hy));
    __nv_bfloat16 lz = __float2bfloat16(v.z - __bfloat162float(hz));
    __nv_bfloat16 lw = __float2bfloat16(v.w - __bfloat162float(hw));
    __nv_bfloat162* hp = (__nv_bfloat162*)h;
    __nv_bfloat162* lp = (__nv_bfloat162*)l;
    hp[i*2+0] = __nv_bfloat162(hx, hy);
    hp[i*2+1] = __nv_bfloat162(hz, hw);
    lp[i*2+0] = __nv_bfloat162(lx, ly);
    lp[i*2+1] = __nv_bfloat162(lz, lw);
}

// ---------------- mma.sync GEMM: Y = A@B^T via 3-term bf16 split ----------------
// M=8192, N=512, K=512. 128x128 CTA tile, BK=64, 256 threads = 8 warps (2m x 4n),
// warp tile 64x32, mma.m16n8k16 bf16, fp32 accum. SW128-swizzled smem tiles.
#define OF_AH 0
#define OF_AL 16384
#define OF_BH 32768
#define OF_BL 49152
#define OF_BIAS 65536
#define GSM_BYTES (65536 + 512 + 128)

template<int ACT>
__global__ __launch_bounds__(256) void gemm_mma(
    const __nv_bfloat16* __restrict__ Ah, const __nv_bfloat16* __restrict__ Al,
    const __nv_bfloat16* __restrict__ Bh, const __nv_bfloat16* __restrict__ Bl,
    const float* __restrict__ bias, float* __restrict__ Y)
{
    extern __shared__ char smem_raw[];
    uint32_t sb0 = smem_u32(smem_raw);
    uint32_t sb  = (sb0 + 127) & ~127u;
    char* smb = smem_raw + (sb - sb0);

    const int tid = threadIdx.x, lid = tid & 31, wid = tid >> 5;
    const int wm = (wid & 1) * 64;        // warp m offset in tile
    const int wn = (wid >> 1) * 32;       // warp n offset in tile
    const int m0 = blockIdx.x * 128, n0 = blockIdx.y * 128;

    float* sbias = (float*)(smb + OF_BIAS);
    if (tid < 128) sbias[tid] = bias[n0 + tid];

    float acc[4][4][4];
#pragma unroll
    for (int mi = 0; mi < 4; mi++)
#pragma unroll
        for (int ni = 0; ni < 4; ni++)
#pragma unroll
            for (int kk = 0; kk < 4; kk++) acc[mi][ni][kk] = 0.f;

    // ldmatrix lane addressing (constant parts)
    const int arow = wm + (lid & 15);             // A: rows, 4 m-tiles stride 16
    const int acolb = (lid >> 4) << 3;            // A: k sub-offset 0/8
    const int brow = wn + (lid & 7);              // B: n rows, 4 n-tiles stride 8
    const int bcolb = (lid & 8);                  // B: k sub-offset 0/8 (lanes 8-15)

    for (int c = 0; c < 8; c++) {
        int k0 = c * 64;
        // load 4 tiles of 128 rows x 64 bf16 (128B rows, SW128), 4 uint4/thread/tile
#pragma unroll
        for (int p = 0; p < 4; p++) {
            int i = tid + p * 256;
            int row = i >> 3, j = i & 7;
            uint32_t off = SWZ128((uint32_t)(row * 128 + j * 16));
            *(uint4*)(smb + OF_AH + off) = *(const uint4*)(Ah + (size_t)(m0 + row) * EE + k0 + j * 8);
            *(uint4*)(smb + OF_AL + off) = *(const uint4*)(Al + (size_t)(m0 + row) * EE + k0 + j * 8);
            *(uint4*)(smb + OF_BH + off) = *(const uint4*)(Bh + (size_t)(n0 + row) * EE + k0 + j * 8);
            *(uint4*)(smb + OF_BL + off) = *(const uint4*)(Bl + (size_t)(n0 + row) * EE + k0 + j * 8);
        }
        __syncthreads();

#pragma unroll
        for (int ks = 0; ks < 4; ks++) {
            uint32_t ah[4][4], al[4][4], bh[4][2], bl[4][2];
            int ak = ks * 16 + acolb;
#pragma unroll
            for (int mi = 0; mi < 4; mi++) {
                uint32_t off = SWZ128((uint32_t)((arow + mi * 16) * 128 + ak * 2));
                ldsm_x4(ah[mi], sb + OF_AH + off);
                ldsm_x4(al[mi], sb + OF_AL + off);
            }
            int bk = ks * 16 + bcolb;
#pragma unroll
            for (int ni = 0; ni < 4; ni++) {
                uint32_t off = SWZ128((uint32_t)((brow + ni * 8) * 128 + bk * 2));
                ldsm_x2(bh[ni], sb + OF_BH + off);
                ldsm_x2(bl[ni], sb + OF_BL + off);
            }
#pragma unroll
            for (int mi = 0; mi < 4; mi++)
#pragma unroll
                for (int ni = 0; ni < 4; ni++) {
                    mma_bf16(acc[mi][ni], ah[mi], bh[ni]);
                    mma_bf16(acc[mi][ni], al[mi], bh[ni]);
                    mma_bf16(acc[mi][ni], ah[mi], bl[ni]);
                }
        }
        __syncthreads();
    }

    // epilogue: fragment layout m16n8: c0,c1 -> row (lid>>2), cols (lid&3)*2 +0/1
    //           c2,c3 -> row (lid>>2)+8
    const int er = lid >> 2, ec = (lid & 3) * 2;
#pragma unroll
    for (int mi = 0; mi < 4; mi++) {
#pragma unroll
        for (int ni = 0; ni < 4; ni++) {
            int nn = wn + ni * 8 + ec;
            float b0 = sbias[nn], b1 = sbias[nn + 1];
            int m1 = m0 + wm + mi * 16 + er;
            float2 v0 = make_float2(acc[mi][ni][0] + b0, acc[mi][ni][1] + b1);
            float2 v1 = make_float2(acc[mi][ni][2] + b0, acc[mi][ni][3] + b1);
            if (ACT) {
                v0.x = (v0.x > 0.f) ? (v0.x + 1.f) : expf(v0.x);
                v0.y = (v0.y > 0.f) ? (v0.y + 1.f) : expf(v0.y);
                v1.x = (v1.x > 0.f) ? (v1.x + 1.f) : expf(v1.x);
                v1.y = (v1.y > 0.f) ? (v1.y + 1.f) : expf(v1.y);
            }
            *(float2*)(Y + (size_t)m1 * EE + n0 + nn) = v0;
            *(float2*)(Y + (size_t)(m1 + 8) * EE + n0 + nn) = v1;
        }
    }
}

// ---------------- Pass A: per-chunk KV outer sums + key sums -------------------
__global__ __launch_bounds__(256) void chunk_sums_kernel()
{
    int blk = blockIdx.x;
    int bh = blk / NCH, c = blk % NCH;
    int b = bh / HH, h = bh % HH;

    extern __shared__ float sm[];
    float* sk = sm;
    float* sv = sm + CHUNK * 65;

    int tid = threadIdx.x;
    const float* kg = g_k + ((size_t)b * TT + (size_t)c * CHUNK) * EE + h * DD;
    const float* vg = g_v + ((size_t)b * TT + (size_t)c * CHUNK) * EE + h * DD;

    for (int i = tid; i < CHUNK * 16; i += 256) {
        int t = i >> 4, d4 = (i & 15) * 4;
        float4 a = *(const float4*)&kg[(size_t)t * EE + d4];
        sk[t * 65 + d4 + 0] = a.x; sk[t * 65 + d4 + 1] = a.y;
        sk[t * 65 + d4 + 2] = a.z; sk[t * 65 + d4 + 3] = a.w;
        float4 w = *(const float4*)&vg[(size_t)t * EE + d4];
        sv[t * 65 + d4 + 0] = w.x; sv[t * 65 + d4 + 1] = w.y;
        sv[t * 65 + d4 + 2] = w.z; sv[t * 65 + d4 + 3] = w.w;
    }
    __syncthreads();

    int d = tid >> 2;
    int eg = (tid & 3) * 16;
    float acc[16];
#pragma unroll
    for (int j = 0; j < 16; j++) acc[j] = 0.f;
    float zacc = 0.f;

    for (int t = 0; t < CHUNK; t++) {
        float kv = sk[t * 65 + d];
        zacc += kv;
        const float* vr = &sv[t * 65 + eg];
#pragma unroll
        for (int j = 0; j < 16; j++) acc[j] += kv * vr[j];
    }

    float* Mout = g_Mc + (size_t)blk * DD * DD + d * DD + eg;
#pragma unroll
    for (int j = 0; j < 16; j++) Mout[j] = acc[j];
    if ((tid & 3) == 0) g_zc[(size_t)blk * DD + d] = zacc;
}

// ---------------- Pass B: exclusive prefix over chunks -------------------------
__global__ void prefix_kernel()
{
    int idx = blockIdx.x * 256 + threadIdx.x;
    const int PER = DD * DD + DD;
    if (idx >= NBH * PER) return;
    int bh = idx / PER;
    int r  = idx % PER;
    if (r < DD * DD) {
        float run = 0.f;
        for (int c = 0; c < NCH; c++) {
            size_t o = (size_t)(bh * NCH + c) * DD * DD + r;
            g_Mp[o] = run;
            run += g_Mc[o];
        }
    } else {
        int d = r - DD * DD;
        float run = 0.f;
        for (int c = 0; c < NCH; c++) {
            size_t o = (size_t)(bh * NCH + c) * DD + d;
            g_zp[o] = run;
            run += g_zc[o];
        }
    }
}

// ---------------- Pass C: per-chunk output ------------------------------------
__global__ __launch_bounds__(256) void chunk_attn_kernel()
{
    int blk = blockIdx.x;
    int bh = blk / NCH, c = blk % NCH;
    int b = bh / HH, h = bh % HH;

    extern __shared__ float sm[];
    float* sq  = sm;
    float* sk  = sq + 128 * 65;
    float* sv  = sk + 128 * 65;
    float* sS  = sv + 128 * 65;
    float* sz  = sS + 64 * 65;
    float* sdi = sz + 64;
    float* sA  = sdi + 128;

    int tid = threadIdx.x;
    const float* qg = g_q + ((size_t)b * TT + (size_t)c * CHUNK) * EE + h * DD;
    const float* kg = g_k + ((size_t)b * TT + (size_t)c * CHUNK) * EE + h * DD;
    const float* vg = g_v + ((size_t)b * TT + (size_t)c * CHUNK) * EE + h * DD;
    const float* Mp = g_Mp + (size_t)blk * DD * DD;
    const float* zp = g_zp + (size_t)blk * DD;

    for (int i = tid; i < CHUNK * 16; i += 256) {
        int t = i >> 4, d4 = (i & 15) * 4;
        float4 a = *(const float4*)&qg[(size_t)t * EE + d4];
        sq[t * 65 + d4 + 0] = a.x; sq[t * 65 + d4 + 1] = a.y;
        sq[t * 65 + d4 + 2] = a.z; sq[t * 65 + d4 + 3] = a.w;
        float4 w = *(const float4*)&kg[(size_t)t * EE + d4];
        sk[t * 65 + d4 + 0] = w.x; sk[t * 65 + d4 + 1] = w.y;
        sk[t * 65 + d4 + 2] = w.z; sk[t * 65 + d4 + 3] = w.w;
        float4 v = *(const float4*)&vg[(size_t)t * EE + d4];
        sv[t * 65 + d4 + 0] = v.x; sv[t * 65 + d4 + 1] = v.y;
        sv[t * 65 + d4 + 2] = v.z; sv[t * 65 + d4 + 3] = v.w;
    }
    for (int i = tid; i < DD * DD; i += 256) {
        sS[(i >> 6) * 65 + (i & 63)] = Mp[i];
    }
    if (tid < DD) sz[tid] = zp[tid];
    __syncthreads();

    for (int i = tid; i < 128 * 128; i += 256) {
        int t = i >> 7, s = i & 127;
        if (s <= t) {
            const float* qr = &sq[t * 65];
            const float* kr = &sk[s * 65];
            float a = 0.f;
#pragma unroll
            for (int dd = 0; dd < DD; dd++) a += qr[dd] * kr[dd];
            sA[t * 128 + s] = a;
        }
    }
    __syncthreads();

    if (tid < 128) {
        int t = tid;
        const float* qr = &sq[t * 65];
        float den = EPSF;
#pragma unroll
        for (int dd = 0; dd < DD; dd++) den += qr[dd] * sz[dd];
        for (int s = 0; s <= t; s++) den += sA[t * 128 + s];
        sdi[t] = 1.f / den;
    }
    __syncthreads();

    float* og = g_attn + ((size_t)b * TT + (size_t)c * CHUNK) * EE + h * DD;
    for (int i = tid; i < 128 * 64; i += 256) {
        int t = i >> 6, e = i & 63;
        const float* qr = &sq[t * 65];
        float acc = 0.f;
#pragma unroll
        for (int dd = 0; dd < DD; dd++) acc += qr[dd] * sS[dd * 65 + e];
        const float* ar = &sA[t * 128];
        for (int s = 0; s <= t; s++) acc += ar[s] * sv[s * 65 + e];
        og[(size_t)t * EE + e] = acc * sdi[t];
    }
}

// ---------------- host ----------------------------------------------------------
extern "C" void kernel_launch(void* const* d_in, const int* in_sizes, int n_in,
                              void* d_out, int out_size)
{
    const float* x  = (const float*)d_in[0];
    const float* Wq = (const float*)d_in[1];
    const float* bq = (const float*)d_in[2];
    const float* Wk = (const float*)d_in[3];
    const float* bk = (const float*)d_in[4];
    const float* Wv = (const float*)d_in[5];
    const float* bv = (const float*)d_in[6];
    const float* Wo = (const float*)d_in[7];
    const float* bo = (const float*)d_in[8];
    float* out = (float*)d_out;

    float *pq, *pk, *pv, *pa;
    cudaGetSymbolAddress((void**)&pq, g_q);
    cudaGetSymbolAddress((void**)&pk, g_k);
    cudaGetSymbolAddress((void**)&pv, g_v);
    cudaGetSymbolAddress((void**)&pa, g_attn);
    __nv_bfloat16 *xh, *xl, *ah, *al, *wh, *wl;
    cudaGetSymbolAddress((void**)&xh, g_xh);
    cudaGetSymbolAddress((void**)&xl, g_xl);
    cudaGetSymbolAddress((void**)&ah, g_ah);
    cudaGetSymbolAddress((void**)&al, g_al);
    cudaGetSymbolAddress((void**)&wh, g_wh);
    cudaGetSymbolAddress((void**)&wl, g_wl);

    cudaFuncSetAttribute(gemm_mma<0>, cudaFuncAttributeMaxDynamicSharedMemorySize, GSM_BYTES);
    cudaFuncSetAttribute(gemm_mma<1>, cudaFuncAttributeMaxDynamicSharedMemorySize, GSM_BYTES);
    cudaFuncSetAttribute(chunk_sums_kernel,
                         cudaFuncAttributeMaxDynamicSharedMemorySize, 2 * 128 * 65 * 4);
    int smC = (3 * 128 * 65 + 64 * 65 + 64 + 128 + 128 * 128) * 4;
    cudaFuncSetAttribute(chunk_attn_kernel,
                         cudaFuncAttributeMaxDynamicSharedMemorySize, smC);

    const int WSZ = EE * EE;            // 262144
    // splits
    split_kernel<<<(MROWS*EE/4 + 255)/256, 256>>>(x,  xh, xl, MROWS*EE/4);
    split_kernel<<<(WSZ/4 + 255)/256, 256>>>(Wq, wh + 0*WSZ, wl + 0*WSZ, WSZ/4);
    split_kernel<<<(WSZ/4 + 255)/256, 256>>>(Wk, wh + 1*WSZ, wl + 1*WSZ, WSZ/4);
    split_kernel<<<(WSZ/4 + 255)/256, 256>>>(Wv, wh + 2*WSZ, wl + 2*WSZ, WSZ/4);
    split_kernel<<<(WSZ/4 + 255)/256, 256>>>(Wo, wh + 3*WSZ, wl + 3*WSZ, WSZ/4);

    dim3 ggrid(MROWS / 128, EE / 128);  // 64 x 4

    gemm_mma<1><<<ggrid, 256, GSM_BYTES>>>(xh, xl, wh + 0*WSZ, wl + 0*WSZ, bq, pq);
    gemm_mma<1><<<ggrid, 256, GSM_BYTES>>>(xh, xl, wh + 1*WSZ, wl + 1*WSZ, bk, pk);
    gemm_mma<0><<<ggrid, 256, GSM_BYTES>>>(xh, xl, wh + 2*WSZ, wl + 2*WSZ, bv, pv);

    chunk_sums_kernel<<<NBH * NCH, 256, 2 * 128 * 65 * 4>>>();

    int totalPref = NBH * (DD * DD + DD);
    prefix_kernel<<<(totalPref + 255) / 256, 256>>>();

    chunk_attn_kernel<<<NBH * NCH, 256, smC>>>();

    split_kernel<<<(MROWS*EE/4 + 255)/256, 256>>>(pa, ah, al, MROWS*EE/4);
    gemm_mma<0><<<ggrid, 256, GSM_BYTES>>>(ah, al, wh + 3*WSZ, wl + 3*WSZ, bo, out);
}

// round 10
// speedup vs baseline: 2.3210x; 1.6011x over previous
#include <cuda_runtime.h>
#include <cuda_bf16.h>
#include <math.h>
#include <stdint.h>

#define BB 2
#define TT 4096
#define EE 512
#define HH 8
#define DD 64
#define CHUNK 128
#define NCH (TT/CHUNK)     // 32
#define NBH (BB*HH)        // 16
#define EPSF 1e-6f
#define MROWS (BB*TT)      // 8192
#define WSZ (EE*EE)

// ---------------- scratch (__device__ globals) ---------------------------------
__device__ float g_q[MROWS*EE];
__device__ float g_k[MROWS*EE];
__device__ float g_v[MROWS*EE];
__device__ float g_Mc[NBH*NCH*DD*DD];
__device__ float g_zc[NBH*NCH*DD];
__device__ float g_Mp[NBH*NCH*DD*DD];
__device__ float g_zp[NBH*NCH*DD];

// bf16 hi/lo splits
__device__ __nv_bfloat16 g_xh[MROWS*EE];
__device__ __nv_bfloat16 g_xl[MROWS*EE];
__device__ __nv_bfloat16 g_ah[MROWS*EE];
__device__ __nv_bfloat16 g_al[MROWS*EE];
__device__ __nv_bfloat16 g_wh[4*WSZ];
__device__ __nv_bfloat16 g_wl[4*WSZ];

// ---------------- helpers -------------------------------------------------------
__device__ __forceinline__ uint32_t smem_u32(const void* p) {
    uint32_t a;
    asm("{ .reg .u64 t; cvta.to.shared.u64 t, %1; cvt.u32.u64 %0, t; }"
        : "=r"(a) : "l"(p));
    return a;
}

#define SWZ128(x) ((x) ^ (((x) >> 3) & 0x70))

__device__ __forceinline__ void cp16(uint32_t dst, const void* src) {
    asm volatile("cp.async.cg.shared.global [%0], [%1], 16;" :: "r"(dst), "l"(src));
}
__device__ __forceinline__ void cp_commit() {
    asm volatile("cp.async.commit_group;" ::: "memory");
}
__device__ __forceinline__ void cp_wait0() {
    asm volatile("cp.async.wait_group 0;" ::: "memory");
}

__device__ __forceinline__ void ldsm_x4(uint32_t r[4], uint32_t addr) {
    asm volatile("ldmatrix.sync.aligned.m8n8.x4.shared.b16 {%0,%1,%2,%3}, [%4];"
                 : "=r"(r[0]), "=r"(r[1]), "=r"(r[2]), "=r"(r[3]) : "r"(addr));
}
// B stored [n][k] (k-contiguous) == col-major KxN: non-trans x2 gives the
// canonical m16n8k16 B fragment.
__device__ __forceinline__ void ldsm_x2(uint32_t r[2], uint32_t addr) {
    asm volatile("ldmatrix.sync.aligned.m8n8.x2.shared.b16 {%0,%1}, [%2];"
                 : "=r"(r[0]), "=r"(r[1]) : "r"(addr));
}
__device__ __forceinline__ void mma_bf16(float c[4], const uint32_t a[4], const uint32_t b[2]) {
    asm volatile(
        "mma.sync.aligned.m16n8k16.row.col.f32.bf16.bf16.f32 "
        "{%0,%1,%2,%3}, {%4,%5,%6,%7}, {%8,%9}, {%0,%1,%2,%3};"
        : "+f"(c[0]), "+f"(c[1]), "+f"(c[2]), "+f"(c[3])
        : "r"(a[0]), "r"(a[1]), "r"(a[2]), "r"(a[3]), "r"(b[0]), "r"(b[1]));
}

// ---------------- split: fp32 -> bf16 hi + bf16 lo ------------------------------
__global__ __launch_bounds__(256) void split_kernel(
    const float* __restrict__ s, __nv_bfloat16* __restrict__ h,
    __nv_bfloat16* __restrict__ l, int n4)
{
    int i = blockIdx.x * 256 + threadIdx.x;
    if (i >= n4) return;
    float4 v = ((const float4*)s)[i];
    __nv_bfloat16 hx = __float2bfloat16(v.x);
    __nv_bfloat16 hy = __float2bfloat16(v.y);
    __nv_bfloat16 hz = __float2bfloat16(v.z);
    __nv_bfloat16 hw = __float2bfloat16(v.w);
    __nv_bfloat16 lx = __float2bfloat16(v.x - __bfloat162float(hx));
    __nv_bfloat16 ly = __float2bfloat16(v.y - __bfloat162float(hy));
    __nv_bfloat16 lz = __float2bfloat16(v.z - __bfloat162float(hz));
    __nv_bfloat16 lw = __float2bfloat16(v.w - __bfloat162float(hw));
    __nv_bfloat162* hp = (__nv_bfloat162*)h;
    __nv_bfloat162* lp = (__nv_bfloat162*)l;
    hp[i*2+0] = __nv_bfloat162(hx, hy);
    hp[i*2+1] = __nv_bfloat162(hz, hw);
    lp[i*2+0] = __nv_bfloat162(lx, ly);
    lp[i*2+1] = __nv_bfloat162(lz, lw);
}

// ---------------- mma.sync GEMM, cp.async double-buffered, multi-output ---------
// M=8192, N=512, K=512 per gemm. blockIdx.y = g*4 + nblk, g selects weight/out.
// 128x128 CTA tile, BK=64, 256 threads = 8 warps (2m x 4n), warp tile 64x32.
#define OF_AH 0
#define OF_AL 16384
#define OF_BH 32768
#define OF_BL 49152
#define STAGE_BYTES 65536
#define OF_BIAS (2*STAGE_BYTES)
#define GSM_BYTES (2*STAGE_BYTES + 512 + 256)

__global__ __launch_bounds__(256, 1) void gemm_mma_multi(
    const __nv_bfloat16* __restrict__ Ah, const __nv_bfloat16* __restrict__ Al,
    const __nv_bfloat16* __restrict__ Wh, const __nv_bfloat16* __restrict__ Wl,
    const float* b0, const float* b1, const float* b2,
    float* Y0, float* Y1, float* Y2, int actmask)
{
    extern __shared__ char smem_raw[];
    uint32_t sb0 = smem_u32(smem_raw);
    uint32_t sb  = (sb0 + 127) & ~127u;
    char* smb = smem_raw + (sb - sb0);

    const int tid = threadIdx.x, lid = tid & 31, wid = tid >> 5;
    const int wm = (wid & 1) * 64;
    const int wn = (wid >> 1) * 32;
    const int g  = blockIdx.y >> 2;
    const int m0 = blockIdx.x * 128, n0 = (blockIdx.y & 3) * 128;

    const __nv_bfloat16* Bh = Wh + (size_t)g * WSZ;
    const __nv_bfloat16* Bl = Wl + (size_t)g * WSZ;
    const float* bias = (g == 0) ? b0 : (g == 1) ? b1 : b2;
    float* Y = (g == 0) ? Y0 : (g == 1) ? Y1 : Y2;
    const bool act = (actmask >> g) & 1;

    float* sbias = (float*)(smb + OF_BIAS);
    if (tid < 128) sbias[tid] = bias[n0 + tid];

    float acc[4][4][4];
#pragma unroll
    for (int mi = 0; mi < 4; mi++)
#pragma unroll
        for (int ni = 0; ni < 4; ni++)
#pragma unroll
            for (int kk = 0; kk < 4; kk++) acc[mi][ni][kk] = 0.f;

    const int arow = wm + (lid & 15);
    const int acolb = (lid >> 4) << 3;
    const int brow = wn + (lid & 7);
    const int bcolb = (lid & 8);

    const int lrow = tid >> 3, lj = tid & 7;   // loader: 2 rows-of-8 per thread
    // loader lambda-ish macro
#define ISSUE_LOAD(st, k0) do {                                                   \
    uint32_t base = sb + (st) * STAGE_BYTES;                                      \
    _Pragma("unroll")                                                             \
    for (int p = 0; p < 4; p++) {                                                 \
        int row = lrow + p * 32;                                                  \
        uint32_t off = SWZ128((uint32_t)(row * 128 + lj * 16));                   \
        size_t ga = (size_t)(m0 + row) * EE + (k0) + lj * 8;                      \
        size_t gb = (size_t)(n0 + row) * EE + (k0) + lj * 8;                      \
        cp16(base + OF_AH + off, Ah + ga);                                        \
        cp16(base + OF_AL + off, Al + ga);                                        \
        cp16(base + OF_BH + off, Bh + gb);                                        \
        cp16(base + OF_BL + off, Bl + gb);                                        \
    }                                                                             \
    cp_commit();                                                                  \
} while (0)

    ISSUE_LOAD(0, 0);
    int cur = 0;
    for (int c = 0; c < 8; c++) {
        cp_wait0();
        __syncthreads();
        if (c < 7) ISSUE_LOAD(cur ^ 1, (c + 1) * 64);

        uint32_t tb = sb + cur * STAGE_BYTES;
#pragma unroll
        for (int ks = 0; ks < 4; ks++) {
            uint32_t ah[4][4], al[4][4], bh[4][2], bl[4][2];
            int ak = ks * 16 + acolb;
#pragma unroll
            for (int mi = 0; mi < 4; mi++) {
                uint32_t off = SWZ128((uint32_t)((arow + mi * 16) * 128 + ak * 2));
                ldsm_x4(ah[mi], tb + OF_AH + off);
                ldsm_x4(al[mi], tb + OF_AL + off);
            }
            int bk = ks * 16 + bcolb;
#pragma unroll
            for (int ni = 0; ni < 4; ni++) {
                uint32_t off = SWZ128((uint32_t)((brow + ni * 8) * 128 + bk * 2));
                ldsm_x2(bh[ni], tb + OF_BH + off);
                ldsm_x2(bl[ni], tb + OF_BL + off);
            }
#pragma unroll
            for (int mi = 0; mi < 4; mi++)
#pragma unroll
                for (int ni = 0; ni < 4; ni++) {
                    mma_bf16(acc[mi][ni], ah[mi], bh[ni]);
                    mma_bf16(acc[mi][ni], al[mi], bh[ni]);
                    mma_bf16(acc[mi][ni], ah[mi], bl[ni]);
                }
        }
        cur ^= 1;
    }
#undef ISSUE_LOAD

    const int er = lid >> 2, ec = (lid & 3) * 2;
#pragma unroll
    for (int mi = 0; mi < 4; mi++) {
#pragma unroll
        for (int ni = 0; ni < 4; ni++) {
            int nn = wn + ni * 8 + ec;
            float bb0 = sbias[nn], bb1 = sbias[nn + 1];
            int m1 = m0 + wm + mi * 16 + er;
            float2 v0 = make_float2(acc[mi][ni][0] + bb0, acc[mi][ni][1] + bb1);
            float2 v1 = make_float2(acc[mi][ni][2] + bb0, acc[mi][ni][3] + bb1);
            if (act) {
                v0.x = (v0.x > 0.f) ? (v0.x + 1.f) : expf(v0.x);
                v0.y = (v0.y > 0.f) ? (v0.y + 1.f) : expf(v0.y);
                v1.x = (v1.x > 0.f) ? (v1.x + 1.f) : expf(v1.x);
                v1.y = (v1.y > 0.f) ? (v1.y + 1.f) : expf(v1.y);
            }
            *(float2*)(Y + (size_t)m1 * EE + n0 + nn) = v0;
            *(float2*)(Y + (size_t)(m1 + 8) * EE + n0 + nn) = v1;
        }
    }
}

// ---------------- Pass A: per-chunk KV outer sums + key sums -------------------
// 256 threads as 16x16; thread (tr,tc) computes 4x4 tile of Mc.
__global__ __launch_bounds__(256) void chunk_sums_kernel()
{
    int blk = blockIdx.x;
    int bh = blk / NCH, c = blk % NCH;
    int b = bh / HH, h = bh % HH;

    extern __shared__ float sm[];
    float* sk = sm;                 // [128][68]
    float* sv = sm + CHUNK * 68;    // [128][68]

    int tid = threadIdx.x;
    const float* kg = g_k + ((size_t)b * TT + (size_t)c * CHUNK) * EE + h * DD;
    const float* vg = g_v + ((size_t)b * TT + (size_t)c * CHUNK) * EE + h * DD;

    for (int i = tid; i < CHUNK * 16; i += 256) {
        int t = i >> 4, d4 = (i & 15) * 4;
        *(float4*)&sk[t * 68 + d4] = *(const float4*)&kg[(size_t)t * EE + d4];
        *(float4*)&sv[t * 68 + d4] = *(const float4*)&vg[(size_t)t * EE + d4];
    }
    __syncthreads();

    int tr = tid >> 4, tc = tid & 15;     // d-base = tr*4, e-base = tc*4
    float acc[4][4];
#pragma unroll
    for (int i = 0; i < 4; i++)
#pragma unroll
        for (int j = 0; j < 4; j++) acc[i][j] = 0.f;
    float z0 = 0.f, z1 = 0.f, z2 = 0.f, z3 = 0.f;

#pragma unroll 4
    for (int t = 0; t < CHUNK; t++) {
        float4 kv = *(const float4*)&sk[t * 68 + tr * 4];
        float4 vv = *(const float4*)&sv[t * 68 + tc * 4];
        float fk[4] = {kv.x, kv.y, kv.z, kv.w};
        float fv[4] = {vv.x, vv.y, vv.z, vv.w};
#pragma unroll
        for (int i = 0; i < 4; i++)
#pragma unroll
            for (int j = 0; j < 4; j++) acc[i][j] += fk[i] * fv[j];
        if (tc == 0) { z0 += kv.x; z1 += kv.y; z2 += kv.z; z3 += kv.w; }
    }

    float* Mout = g_Mc + (size_t)blk * DD * DD;
#pragma unroll
    for (int i = 0; i < 4; i++) {
        float4 o = make_float4(acc[i][0], acc[i][1], acc[i][2], acc[i][3]);
        *(float4*)&Mout[(tr * 4 + i) * DD + tc * 4] = o;
    }
    if (tc == 0) {
        float* zo = g_zc + (size_t)blk * DD + tr * 4;
        zo[0] = z0; zo[1] = z1; zo[2] = z2; zo[3] = z3;
    }
}

// ---------------- Pass B: exclusive prefix over chunks -------------------------
__global__ void prefix_kernel()
{
    int idx = blockIdx.x * 256 + threadIdx.x;
    const int PER = DD * DD + DD;
    if (idx >= NBH * PER) return;
    int bh = idx / PER;
    int r  = idx % PER;
    if (r < DD * DD) {
        float run = 0.f;
        for (int c = 0; c < NCH; c++) {
            size_t o = (size_t)(bh * NCH + c) * DD * DD + r;
            g_Mp[o] = run;
            run += g_Mc[o];
        }
    } else {
        int d = r - DD * DD;
        float run = 0.f;
        for (int c = 0; c < NCH; c++) {
            size_t o = (size_t)(bh * NCH + c) * DD + d;
            g_zp[o] = run;
            run += g_zc[o];
        }
    }
}

// ---------------- Pass C: per-chunk output (writes bf16 hi/lo directly) --------
// smem layout (floats):
#define SQT 0                    // [64][132] q transposed (dd-major)
#define SKT 8448                 // [64][132]
#define SVX 16896                // [128][68]
#define SSX 25600                // [64][68]
#define SZX 29952                // [64]
#define SDI 30016                // [128]
#define SAT 30144                // [128][132]  A^T (s-major), zeros above diag
#define SMC_FLOATS 47040

__global__ __launch_bounds__(256, 1) void chunk_attn_kernel()
{
    int blk = blockIdx.x;
    int bh = blk / NCH, c = blk % NCH;
    int b = bh / HH, h = bh % HH;

    extern __shared__ float sm[];
    int tid = threadIdx.x;

    const float* qg = g_q + ((size_t)b * TT + (size_t)c * CHUNK) * EE + h * DD;
    const float* kg = g_k + ((size_t)b * TT + (size_t)c * CHUNK) * EE + h * DD;
    const float* vg = g_v + ((size_t)b * TT + (size_t)c * CHUNK) * EE + h * DD;
    const float* Mp = g_Mp + (size_t)blk * DD * DD;
    const float* zp = g_zp + (size_t)blk * DD;

    // q,k transposed loads (lanes span t -> conflict-free smem writes)
    for (int i = tid; i < CHUNK * 16; i += 256) {
        int t = i & 127, d4 = (i >> 7) << 2;
        float4 a = *(const float4*)&qg[(size_t)t * EE + d4];
        sm[SQT + (d4 + 0) * 132 + t] = a.x;
        sm[SQT + (d4 + 1) * 132 + t] = a.y;
        sm[SQT + (d4 + 2) * 132 + t] = a.z;
        sm[SQT + (d4 + 3) * 132 + t] = a.w;
        float4 w = *(const float4*)&kg[(size_t)t * EE + d4];
        sm[SKT + (d4 + 0) * 132 + t] = w.x;
        sm[SKT + (d4 + 1) * 132 + t] = w.y;
        sm[SKT + (d4 + 2) * 132 + t] = w.z;
        sm[SKT + (d4 + 3) * 132 + t] = w.w;
    }
    // v row-major
    for (int i = tid; i < CHUNK * 16; i += 256) {
        int t = i >> 4, e4 = (i & 15) << 2;
        *(float4*)&sm[SVX + t * 68 + e4] = *(const float4*)&vg[(size_t)t * EE + e4];
    }
    for (int i = tid; i < DD * DD; i += 256)
        sm[SSX + (i >> 6) * 68 + (i & 63)] = Mp[i];
    if (tid < DD) sm[SZX + tid] = zp[tid];
    __syncthreads();

    // ---- A = Q K^T, stored transposed AT[s][t], zeros for s > t ----
    {
        int tr = tid >> 4, tc = tid & 15;
        int t0 = tr * 8, s0 = tc * 8;
        float a[8][8];
#pragma unroll
        for (int i = 0; i < 8; i++)
#pragma unroll
            for (int j = 0; j < 8; j++) a[i][j] = 0.f;

        if (s0 < t0 + 8) {
#pragma unroll 4
            for (int dd = 0; dd < DD; dd++) {
                float4 q0 = *(const float4*)&sm[SQT + dd * 132 + t0];
                float4 q1 = *(const float4*)&sm[SQT + dd * 132 + t0 + 4];
                float4 k0 = *(const float4*)&sm[SKT + dd * 132 + s0];
                float4 k1 = *(const float4*)&sm[SKT + dd * 132 + s0 + 4];
                float fq[8] = {q0.x, q0.y, q0.z, q0.w, q1.x, q1.y, q1.z, q1.w};
                float fk[8] = {k0.x, k0.y, k0.z, k0.w, k1.x, k1.y, k1.z, k1.w};
#pragma unroll
                for (int i = 0; i < 8; i++)
#pragma unroll
                    for (int j = 0; j < 8; j++) a[i][j] += fq[i] * fk[j];
            }
        }
        // store AT with lane rotation over i to avoid same-bank across tc
#pragma unroll
        for (int j = 0; j < 8; j++) {
            int s = s0 + j;
#pragma unroll
            for (int i = 0; i < 8; i++) {
                int ii = (i + tc) & 7;
                int t = t0 + ii;
                sm[SAT + s * 132 + t] = (s <= t) ? a[ii][j] : 0.f;
            }
        }
    }
    __syncthreads();

    // ---- denominators ----
    if (tid < CHUNK) {
        int t = tid;
        float den = EPSF;
#pragma unroll 8
        for (int dd = 0; dd < DD; dd++)
            den += sm[SQT + dd * 132 + t] * sm[SZX + dd];
#pragma unroll 8
        for (int s = 0; s < CHUNK; s++)
            den += sm[SAT + s * 132 + t];
        sm[SDI + t] = 1.f / den;
    }
    __syncthreads();

    // ---- out = (Q S_pref + A_causal V) * inv_den, split to bf16 hi/lo ----
    {
        int tr = tid >> 4, tc = tid & 15;
        int t0 = tr * 8, e0 = tc * 4;
        float o[8][4];
#pragma unroll
        for (int i = 0; i < 8; i++)
#pragma unroll
            for (int j = 0; j < 4; j++) o[i][j] = 0.f;

        int smax = t0 + 8;
        for (int s = 0; s < smax; s++) {
            float4 a0 = *(const float4*)&sm[SAT + s * 132 + t0];
            float4 a1 = *(const float4*)&sm[SAT + s * 132 + t0 + 4];
            float4 vv = *(const float4*)&sm[SVX + s * 68 + e0];
            float fa[8] = {a0.x, a0.y, a0.z, a0.w, a1.x, a1.y, a1.z, a1.w};
            float fv[4] = {vv.x, vv.y, vv.z, vv.w};
#pragma unroll
            for (int i = 0; i < 8; i++)
#pragma unroll
                for (int j = 0; j < 4; j++) o[i][j] += fa[i] * fv[j];
        }
#pragma unroll 4
        for (int dd = 0; dd < DD; dd++) {
            float4 q0 = *(const float4*)&sm[SQT + dd * 132 + t0];
            float4 q1 = *(const float4*)&sm[SQT + dd * 132 + t0 + 4];
            float4 Sv = *(const float4*)&sm[SSX + dd * 68 + e0];
            float fq[8] = {q0.x, q0.y, q0.z, q0.w, q1.x, q1.y, q1.z, q1.w};
            float fS[4] = {Sv.x, Sv.y, Sv.z, Sv.w};
#pragma unroll
            for (int i = 0; i < 8; i++)
#pragma unroll
                for (int j = 0; j < 4; j++) o[i][j] += fq[i] * fS[j];
        }

        size_t rbase = ((size_t)b * TT + (size_t)c * CHUNK) * EE + h * DD + e0;
#pragma unroll
        for (int i = 0; i < 8; i++) {
            int t = t0 + i;
            float inv = sm[SDI + t];
            size_t idx = rbase + (size_t)t * EE;
            float f[4];
#pragma unroll
            for (int j = 0; j < 4; j++) f[j] = o[i][j] * inv;
            __nv_bfloat16 hi[4], lo[4];
#pragma unroll
            for (int j = 0; j < 4; j++) {
                hi[j] = __float2bfloat16(f[j]);
                lo[j] = __float2bfloat16(f[j] - __bfloat162float(hi[j]));
            }
            *(__nv_bfloat162*)&g_ah[idx]     = __nv_bfloat162(hi[0], hi[1]);
            *(__nv_bfloat162*)&g_ah[idx + 2] = __nv_bfloat162(hi[2], hi[3]);
            *(__nv_bfloat162*)&g_al[idx]     = __nv_bfloat162(lo[0], lo[1]);
            *(__nv_bfloat162*)&g_al[idx + 2] = __nv_bfloat162(lo[2], lo[3]);
        }
    }
}

// ---------------- host ----------------------------------------------------------
extern "C" void kernel_launch(void* const* d_in, const int* in_sizes, int n_in,
                              void* d_out, int out_size)
{
    const float* x  = (const float*)d_in[0];
    const float* Wq = (const float*)d_in[1];
    const float* bq = (const float*)d_in[2];
    const float* Wk = (const float*)d_in[3];
    const float* bk = (const float*)d_in[4];
    const float* Wv = (const float*)d_in[5];
    const float* bv = (const float*)d_in[6];
    const float* Wo = (const float*)d_in[7];
    const float* bo = (const float*)d_in[8];
    float* out = (float*)d_out;

    float *pq, *pk, *pv;
    cudaGetSymbolAddress((void**)&pq, g_q);
    cudaGetSymbolAddress((void**)&pk, g_k);
    cudaGetSymbolAddress((void**)&pv, g_v);
    __nv_bfloat16 *xh, *xl, *ah, *al, *wh, *wl;
    cudaGetSymbolAddress((void**)&xh, g_xh);
    cudaGetSymbolAddress((void**)&xl, g_xl);
    cudaGetSymbolAddress((void**)&ah, g_ah);
    cudaGetSymbolAddress((void**)&al, g_al);
    cudaGetSymbolAddress((void**)&wh, g_wh);
    cudaGetSymbolAddress((void**)&wl, g_wl);

    cudaFuncSetAttribute(gemm_mma_multi, cudaFuncAttributeMaxDynamicSharedMemorySize, GSM_BYTES);
    cudaFuncSetAttribute(chunk_sums_kernel,
                         cudaFuncAttributeMaxDynamicSharedMemorySize, 2 * 128 * 68 * 4);
    cudaFuncSetAttribute(chunk_attn_kernel,
                         cudaFuncAttributeMaxDynamicSharedMemorySize, SMC_FLOATS * 4);

    // splits
    split_kernel<<<(MROWS*EE/4 + 255)/256, 256>>>(x,  xh, xl, MROWS*EE/4);
    split_kernel<<<(WSZ/4 + 255)/256, 256>>>(Wq, wh + 0*WSZ, wl + 0*WSZ, WSZ/4);
    split_kernel<<<(WSZ/4 + 255)/256, 256>>>(Wk, wh + 1*WSZ, wl + 1*WSZ, WSZ/4);
    split_kernel<<<(WSZ/4 + 255)/256, 256>>>(Wv, wh + 2*WSZ, wl + 2*WSZ, WSZ/4);
    split_kernel<<<(WSZ/4 + 255)/256, 256>>>(Wo, wh + 3*WSZ, wl + 3*WSZ, WSZ/4);

    // fused QKV projection (12 n-blocks: 4 per gemm, g = y/4)
    dim3 gq(MROWS / 128, 12);
    gemm_mma_multi<<<gq, 256, GSM_BYTES>>>(xh, xl, wh, wl, bq, bk, bv,
                                           pq, pk, pv, 0x3);

    chunk_sums_kernel<<<NBH * NCH, 256, 2 * 128 * 68 * 4>>>();

    int totalPref = NBH * (DD * DD + DD);
    prefix_kernel<<<(totalPref + 255) / 256, 256>>>();

    chunk_attn_kernel<<<NBH * NCH, 256, SMC_FLOATS * 4>>>();

    // output projection (g=0 only)
    dim3 go(MROWS / 128, 4);
    gemm_mma_multi<<<go, 256, GSM_BYTES>>>(ah, al, wh + 3*WSZ, wl + 3*WSZ,
                                           bo, bo, bo, out, out, out, 0x0);
}

// round 11
// speedup vs baseline: 3.2639x; 1.4063x over previous
#include <cuda_runtime.h>
#include <cuda_fp16.h>
#include <math.h>
#include <stdint.h>

#define BB 2
#define TT 4096
#define EE 512
#define HH 8
#define DD 64
#define CHUNK 128
#define NCH (TT/CHUNK)     // 32
#define NBH (BB*HH)        // 16
#define EPSF 1e-6f
#define MROWS (BB*TT)      // 8192
#define WSZ (EE*EE)

// ---------------- scratch (__device__ globals) ---------------------------------
__device__ float g_q[MROWS*EE];
__device__ float g_k[MROWS*EE];
__device__ float g_v[MROWS*EE];
__device__ float g_Mc[NBH*NCH*DD*DD];
__device__ float g_zc[NBH*NCH*DD];
__device__ float g_Mp[NBH*NCH*DD*DD];
__device__ float g_zp[NBH*NCH*DD];

// fp16 operands
__device__ __half g_xf[MROWS*EE];
__device__ __half g_af[MROWS*EE];
__device__ __half g_wf[4*WSZ];

// ---------------- helpers -------------------------------------------------------
__device__ __forceinline__ uint32_t smem_u32(const void* p) {
    uint32_t a;
    asm("{ .reg .u64 t; cvta.to.shared.u64 t, %1; cvt.u32.u64 %0, t; }"
        : "=r"(a) : "l"(p));
    return a;
}

#define SWZ128(x) ((x) ^ (((x) >> 3) & 0x70))

__device__ __forceinline__ void cp16(uint32_t dst, const void* src) {
    asm volatile("cp.async.cg.shared.global [%0], [%1], 16;" :: "r"(dst), "l"(src));
}
__device__ __forceinline__ void cp_commit() {
    asm volatile("cp.async.commit_group;" ::: "memory");
}
__device__ __forceinline__ void cp_wait0() {
    asm volatile("cp.async.wait_group 0;" ::: "memory");
}

__device__ __forceinline__ void ldsm_x4(uint32_t r[4], uint32_t addr) {
    asm volatile("ldmatrix.sync.aligned.m8n8.x4.shared.b16 {%0,%1,%2,%3}, [%4];"
                 : "=r"(r[0]), "=r"(r[1]), "=r"(r[2]), "=r"(r[3]) : "r"(addr));
}
// W stored [n][k] (k-contiguous) == col-major KxN: non-trans x2 gives the
// canonical m16n8k16 B fragment.
__device__ __forceinline__ void ldsm_x2(uint32_t r[2], uint32_t addr) {
    asm volatile("ldmatrix.sync.aligned.m8n8.x2.shared.b16 {%0,%1}, [%2];"
                 : "=r"(r[0]), "=r"(r[1]) : "r"(addr));
}
__device__ __forceinline__ void mma_f16(float c[4], const uint32_t a[4], const uint32_t b[2]) {
    asm volatile(
        "mma.sync.aligned.m16n8k16.row.col.f32.f16.f16.f32 "
        "{%0,%1,%2,%3}, {%4,%5,%6,%7}, {%8,%9}, {%0,%1,%2,%3};"
        : "+f"(c[0]), "+f"(c[1]), "+f"(c[2]), "+f"(c[3])
        : "r"(a[0]), "r"(a[1]), "r"(a[2]), "r"(a[3]), "r"(b[0]), "r"(b[1]));
}

// ---------------- convert: fp32 -> fp16 -----------------------------------------
__global__ __launch_bounds__(256) void cvt16_kernel(
    const float* __restrict__ s, __half* __restrict__ d, int n4)
{
    int i = blockIdx.x * 256 + threadIdx.x;
    if (i >= n4) return;
    float4 v = ((const float4*)s)[i];
    __half2* dp = (__half2*)d;
    dp[i*2+0] = __floats2half2_rn(v.x, v.y);
    dp[i*2+1] = __floats2half2_rn(v.z, v.w);
}

// all 4 weight matrices in one launch (blockIdx.y selects)
__global__ __launch_bounds__(256) void cvtw_kernel(
    const float* __restrict__ w0, const float* __restrict__ w1,
    const float* __restrict__ w2, const float* __restrict__ w3,
    __half* __restrict__ d)
{
    int g = blockIdx.y;
    const float* s = (g == 0) ? w0 : (g == 1) ? w1 : (g == 2) ? w2 : w3;
    int i = blockIdx.x * 256 + threadIdx.x;
    if (i >= WSZ/4) return;
    float4 v = ((const float4*)s)[i];
    __half2* dp = (__half2*)(d + (size_t)g * WSZ);
    dp[i*2+0] = __floats2half2_rn(v.x, v.y);
    dp[i*2+1] = __floats2half2_rn(v.z, v.w);
}

// ---------------- mma.sync fp16 GEMM, cp.async double-buffered, multi-output ----
// M=8192, N=512, K=512 per gemm. blockIdx.y = g*4 + nblk, g selects weight/out.
// 128x128 CTA tile, BK=64, 256 threads = 8 warps (2m x 4n), warp tile 64x32.
#define OF_A 0
#define OF_B 16384
#define STAGE_BYTES 32768
#define OF_BIAS (2*STAGE_BYTES)
#define GSM_BYTES (2*STAGE_BYTES + 512 + 256)

__global__ __launch_bounds__(256, 2) void gemm_f16(
    const __half* __restrict__ Af, const __half* __restrict__ Wf,
    const float* b0, const float* b1, const float* b2,
    float* Y0, float* Y1, float* Y2, int actmask)
{
    extern __shared__ char smem_raw[];
    uint32_t sb0 = smem_u32(smem_raw);
    uint32_t sb  = (sb0 + 127) & ~127u;
    char* smb = smem_raw + (sb - sb0);

    const int tid = threadIdx.x, lid = tid & 31, wid = tid >> 5;
    const int wm = (wid & 1) * 64;
    const int wn = (wid >> 1) * 32;
    const int g  = blockIdx.y >> 2;
    const int m0 = blockIdx.x * 128, n0 = (blockIdx.y & 3) * 128;

    const __half* Bf = Wf + (size_t)g * WSZ;
    const float* bias = (g == 0) ? b0 : (g == 1) ? b1 : b2;
    float* Y = (g == 0) ? Y0 : (g == 1) ? Y1 : Y2;
    const bool act = (actmask >> g) & 1;

    float* sbias = (float*)(smb + OF_BIAS);
    if (tid < 128) sbias[tid] = bias[n0 + tid];

    float acc[4][4][4];
#pragma unroll
    for (int mi = 0; mi < 4; mi++)
#pragma unroll
        for (int ni = 0; ni < 4; ni++)
#pragma unroll
            for (int kk = 0; kk < 4; kk++) acc[mi][ni][kk] = 0.f;

    const int arow = wm + (lid & 15);
    const int acolb = (lid >> 4) << 3;
    const int brow = wn + (lid & 7);
    const int bcolb = (lid & 8);

    const int lrow = tid >> 3, lj = tid & 7;
#define ISSUE_LOAD(st, k0) do {                                                   \
    uint32_t base = sb + (st) * STAGE_BYTES;                                      \
    _Pragma("unroll")                                                             \
    for (int p = 0; p < 4; p++) {                                                 \
        int row = lrow + p * 32;                                                  \
        uint32_t off = SWZ128((uint32_t)(row * 128 + lj * 16));                   \
        cp16(base + OF_A + off, Af + (size_t)(m0 + row) * EE + (k0) + lj * 8);    \
        cp16(base + OF_B + off, Bf + (size_t)(n0 + row) * EE + (k0) + lj * 8);    \
    }                                                                             \
    cp_commit();                                                                  \
} while (0)

    ISSUE_LOAD(0, 0);
    int cur = 0;
    for (int c = 0; c < 8; c++) {
        cp_wait0();
        __syncthreads();
        if (c < 7) ISSUE_LOAD(cur ^ 1, (c + 1) * 64);

        uint32_t tb = sb + cur * STAGE_BYTES;
#pragma unroll
        for (int ks = 0; ks < 4; ks++) {
            uint32_t ar[4][4], br[4][2];
            int ak = ks * 16 + acolb;
#pragma unroll
            for (int mi = 0; mi < 4; mi++) {
                uint32_t off = SWZ128((uint32_t)((arow + mi * 16) * 128 + ak * 2));
                ldsm_x4(ar[mi], tb + OF_A + off);
            }
            int bk = ks * 16 + bcolb;
#pragma unroll
            for (int ni = 0; ni < 4; ni++) {
                uint32_t off = SWZ128((uint32_t)((brow + ni * 8) * 128 + bk * 2));
                ldsm_x2(br[ni], tb + OF_B + off);
            }
#pragma unroll
            for (int mi = 0; mi < 4; mi++)
#pragma unroll
                for (int ni = 0; ni < 4; ni++)
                    mma_f16(acc[mi][ni], ar[mi], br[ni]);
        }
        cur ^= 1;
    }
#undef ISSUE_LOAD

    const int er = lid >> 2, ec = (lid & 3) * 2;
#pragma unroll
    for (int mi = 0; mi < 4; mi++) {
#pragma unroll
        for (int ni = 0; ni < 4; ni++) {
            int nn = wn + ni * 8 + ec;
            float bb0 = sbias[nn], bb1 = sbias[nn + 1];
            int m1 = m0 + wm + mi * 16 + er;
            float2 v0 = make_float2(acc[mi][ni][0] + bb0, acc[mi][ni][1] + bb1);
            float2 v1 = make_float2(acc[mi][ni][2] + bb0, acc[mi][ni][3] + bb1);
            if (act) {
                v0.x = (v0.x > 0.f) ? (v0.x + 1.f) : expf(v0.x);
                v0.y = (v0.y > 0.f) ? (v0.y + 1.f) : expf(v0.y);
                v1.x = (v1.x > 0.f) ? (v1.x + 1.f) : expf(v1.x);
                v1.y = (v1.y > 0.f) ? (v1.y + 1.f) : expf(v1.y);
            }
            *(float2*)(Y + (size_t)m1 * EE + n0 + nn) = v0;
            *(float2*)(Y + (size_t)(m1 + 8) * EE + n0 + nn) = v1;
        }
    }
}

// ---------------- Pass A: per-chunk KV outer sums + key sums -------------------
__global__ __launch_bounds__(256) void chunk_sums_kernel()
{
    int blk = blockIdx.x;
    int bh = blk / NCH, c = blk % NCH;
    int b = bh / HH, h = bh % HH;

    extern __shared__ float sm[];
    float* sk = sm;                 // [128][68]
    float* sv = sm + CHUNK * 68;    // [128][68]

    int tid = threadIdx.x;
    const float* kg = g_k + ((size_t)b * TT + (size_t)c * CHUNK) * EE + h * DD;
    const float* vg = g_v + ((size_t)b * TT + (size_t)c * CHUNK) * EE + h * DD;

    for (int i = tid; i < CHUNK * 16; i += 256) {
        int t = i >> 4, d4 = (i & 15) * 4;
        *(float4*)&sk[t * 68 + d4] = *(const float4*)&kg[(size_t)t * EE + d4];
        *(float4*)&sv[t * 68 + d4] = *(const float4*)&vg[(size_t)t * EE + d4];
    }
    __syncthreads();

    int tr = tid >> 4, tc = tid & 15;
    float acc[4][4];
#pragma unroll
    for (int i = 0; i < 4; i++)
#pragma unroll
        for (int j = 0; j < 4; j++) acc[i][j] = 0.f;
    float z0 = 0.f, z1 = 0.f, z2 = 0.f, z3 = 0.f;

#pragma unroll 4
    for (int t = 0; t < CHUNK; t++) {
        float4 kv = *(const float4*)&sk[t * 68 + tr * 4];
        float4 vv = *(const float4*)&sv[t * 68 + tc * 4];
        float fk[4] = {kv.x, kv.y, kv.z, kv.w};
        float fv[4] = {vv.x, vv.y, vv.z, vv.w};
#pragma unroll
        for (int i = 0; i < 4; i++)
#pragma unroll
            for (int j = 0; j < 4; j++) acc[i][j] += fk[i] * fv[j];
        if (tc == 0) { z0 += kv.x; z1 += kv.y; z2 += kv.z; z3 += kv.w; }
    }

    float* Mout = g_Mc + (size_t)blk * DD * DD;
#pragma unroll
    for (int i = 0; i < 4; i++) {
        float4 o = make_float4(acc[i][0], acc[i][1], acc[i][2], acc[i][3]);
        *(float4*)&Mout[(tr * 4 + i) * DD + tc * 4] = o;
    }
    if (tc == 0) {
        float* zo = g_zc + (size_t)blk * DD + tr * 4;
        zo[0] = z0; zo[1] = z1; zo[2] = z2; zo[3] = z3;
    }
}

// ---------------- Pass B: exclusive prefix over chunks -------------------------
__global__ void prefix_kernel()
{
    int idx = blockIdx.x * 256 + threadIdx.x;
    const int PER = DD * DD + DD;
    if (idx >= NBH * PER) return;
    int bh = idx / PER;
    int r  = idx % PER;
    if (r < DD * DD) {
        float run = 0.f;
        for (int c = 0; c < NCH; c++) {
            size_t o = (size_t)(bh * NCH + c) * DD * DD + r;
            g_Mp[o] = run;
            run += g_Mc[o];
        }
    } else {
        int d = r - DD * DD;
        float run = 0.f;
        for (int c = 0; c < NCH; c++) {
            size_t o = (size_t)(bh * NCH + c) * DD + d;
            g_zp[o] = run;
            run += g_zc[o];
        }
    }
}

// ---------------- Pass C: per-chunk output (writes fp16 directly) --------------
#define SQT 0                    // [64][132] q transposed (dd-major)
#define SKT 8448                 // [64][132]
#define SVX 16896                // [128][68]
#define SSX 25600                // [64][68]
#define SZX 29952                // [64]
#define SDI 30016                // [128]
#define SAT 30144                // [128][132]  A^T (s-major), zeros above diag
#define SMC_FLOATS 47040

__global__ __launch_bounds__(256, 1) void chunk_attn_kernel()
{
    int blk = blockIdx.x;
    int bh = blk / NCH, c = blk % NCH;
    int b = bh / HH, h = bh % HH;

    extern __shared__ float sm[];
    int tid = threadIdx.x;

    const float* qg = g_q + ((size_t)b * TT + (size_t)c * CHUNK) * EE + h * DD;
    const float* kg = g_k + ((size_t)b * TT + (size_t)c * CHUNK) * EE + h * DD;
    const float* vg = g_v + ((size_t)b * TT + (size_t)c * CHUNK) * EE + h * DD;
    const float* Mp = g_Mp + (size_t)blk * DD * DD;
    const float* zp = g_zp + (size_t)blk * DD;

    for (int i = tid; i < CHUNK * 16; i += 256) {
        int t = i & 127, d4 = (i >> 7) << 2;
        float4 a = *(const float4*)&qg[(size_t)t * EE + d4];
        sm[SQT + (d4 + 0) * 132 + t] = a.x;
        sm[SQT + (d4 + 1) * 132 + t] = a.y;
        sm[SQT + (d4 + 2) * 132 + t] = a.z;
        sm[SQT + (d4 + 3) * 132 + t] = a.w;
        float4 w = *(const float4*)&kg[(size_t)t * EE + d4];
        sm[SKT + (d4 + 0) * 132 + t] = w.x;
        sm[SKT + (d4 + 1) * 132 + t] = w.y;
        sm[SKT + (d4 + 2) * 132 + t] = w.z;
        sm[SKT + (d4 + 3) * 132 + t] = w.w;
    }
    for (int i = tid; i < CHUNK * 16; i += 256) {
        int t = i >> 4, e4 = (i & 15) << 2;
        *(float4*)&sm[SVX + t * 68 + e4] = *(const float4*)&vg[(size_t)t * EE + e4];
    }
    for (int i = tid; i < DD * DD; i += 256)
        sm[SSX + (i >> 6) * 68 + (i & 63)] = Mp[i];
    if (tid < DD) sm[SZX + tid] = zp[tid];
    __syncthreads();

    // ---- A = Q K^T, stored transposed AT[s][t], zeros for s > t ----
    {
        int tr = tid >> 4, tc = tid & 15;
        int t0 = tr * 8, s0 = tc * 8;
        float a[8][8];
#pragma unroll
        for (int i = 0; i < 8; i++)
#pragma unroll
            for (int j = 0; j < 8; j++) a[i][j] = 0.f;

        if (s0 < t0 + 8) {
#pragma unroll 4
            for (int dd = 0; dd < DD; dd++) {
                float4 q0 = *(const float4*)&sm[SQT + dd * 132 + t0];
                float4 q1 = *(const float4*)&sm[SQT + dd * 132 + t0 + 4];
                float4 k0 = *(const float4*)&sm[SKT + dd * 132 + s0];
                float4 k1 = *(const float4*)&sm[SKT + dd * 132 + s0 + 4];
                float fq[8] = {q0.x, q0.y, q0.z, q0.w, q1.x, q1.y, q1.z, q1.w};
                float fk[8] = {k0.x, k0.y, k0.z, k0.w, k1.x, k1.y, k1.z, k1.w};
#pragma unroll
                for (int i = 0; i < 8; i++)
#pragma unroll
                    for (int j = 0; j < 8; j++) a[i][j] += fq[i] * fk[j];
            }
        }
#pragma unroll
        for (int j = 0; j < 8; j++) {
            int s = s0 + j;
#pragma unroll
            for (int i = 0; i < 8; i++) {
                int ii = (i + tc) & 7;
                int t = t0 + ii;
                sm[SAT + s * 132 + t] = (s <= t) ? a[ii][j] : 0.f;
            }
        }
    }
    __syncthreads();

    // ---- denominators ----
    if (tid < CHUNK) {
        int t = tid;
        float den = EPSF;
#pragma unroll 8
        for (int dd = 0; dd < DD; dd++)
            den += sm[SQT + dd * 132 + t] * sm[SZX + dd];
#pragma unroll 8
        for (int s = 0; s < CHUNK; s++)
            den += sm[SAT + s * 132 + t];
        sm[SDI + t] = 1.f / den;
    }
    __syncthreads();

    // ---- out = (Q S_pref + A_causal V) * inv_den, write fp16 ----
    {
        int tr = tid >> 4, tc = tid & 15;
        int t0 = tr * 8, e0 = tc * 4;
        float o[8][4];
#pragma unroll
        for (int i = 0; i < 8; i++)
#pragma unroll
            for (int j = 0; j < 4; j++) o[i][j] = 0.f;

        int smax = t0 + 8;
        for (int s = 0; s < smax; s++) {
            float4 a0 = *(const float4*)&sm[SAT + s * 132 + t0];
            float4 a1 = *(const float4*)&sm[SAT + s * 132 + t0 + 4];
            float4 vv = *(const float4*)&sm[SVX + s * 68 + e0];
            float fa[8] = {a0.x, a0.y, a0.z, a0.w, a1.x, a1.y, a1.z, a1.w};
            float fv[4] = {vv.x, vv.y, vv.z, vv.w};
#pragma unroll
            for (int i = 0; i < 8; i++)
#pragma unroll
                for (int j = 0; j < 4; j++) o[i][j] += fa[i] * fv[j];
        }
#pragma unroll 4
        for (int dd = 0; dd < DD; dd++) {
            float4 q0 = *(const float4*)&sm[SQT + dd * 132 + t0];
            float4 q1 = *(const float4*)&sm[SQT + dd * 132 + t0 + 4];
            float4 Sv = *(const float4*)&sm[SSX + dd * 68 + e0];
            float fq[8] = {q0.x, q0.y, q0.z, q0.w, q1.x, q1.y, q1.z, q1.w};
            float fS[4] = {Sv.x, Sv.y, Sv.z, Sv.w};
#pragma unroll
            for (int i = 0; i < 8; i++)
#pragma unroll
                for (int j = 0; j < 4; j++) o[i][j] += fq[i] * fS[j];
        }

        size_t rbase = ((size_t)b * TT + (size_t)c * CHUNK) * EE + h * DD + e0;
#pragma unroll
        for (int i = 0; i < 8; i++) {
            int t = t0 + i;
            float inv = sm[SDI + t];
            size_t idx = rbase + (size_t)t * EE;
            *(__half2*)&g_af[idx]     = __floats2half2_rn(o[i][0] * inv, o[i][1] * inv);
            *(__half2*)&g_af[idx + 2] = __floats2half2_rn(o[i][2] * inv, o[i][3] * inv);
        }
    }
}

// ---------------- host ----------------------------------------------------------
extern "C" void kernel_launch(void* const* d_in, const int* in_sizes, int n_in,
                              void* d_out, int out_size)
{
    const float* x  = (const float*)d_in[0];
    const float* Wq = (const float*)d_in[1];
    const float* bq = (const float*)d_in[2];
    const float* Wk = (const float*)d_in[3];
    const float* bk = (const float*)d_in[4];
    const float* Wv = (const float*)d_in[5];
    const float* bv = (const float*)d_in[6];
    const float* Wo = (const float*)d_in[7];
    const float* bo = (const float*)d_in[8];
    float* out = (float*)d_out;

    float *pq, *pk, *pv;
    cudaGetSymbolAddress((void**)&pq, g_q);
    cudaGetSymbolAddress((void**)&pk, g_k);
    cudaGetSymbolAddress((void**)&pv, g_v);
    __half *xf, *af, *wf;
    cudaGetSymbolAddress((void**)&xf, g_xf);
    cudaGetSymbolAddress((void**)&af, g_af);
    cudaGetSymbolAddress((void**)&wf, g_wf);

    cudaFuncSetAttribute(gemm_f16, cudaFuncAttributeMaxDynamicSharedMemorySize, GSM_BYTES);
    cudaFuncSetAttribute(chunk_sums_kernel,
                         cudaFuncAttributeMaxDynamicSharedMemorySize, 2 * 128 * 68 * 4);
    cudaFuncSetAttribute(chunk_attn_kernel,
                         cudaFuncAttributeMaxDynamicSharedMemorySize, SMC_FLOATS * 4);

    // converts
    cvt16_kernel<<<(MROWS*EE/4 + 255)/256, 256>>>(x, xf, MROWS*EE/4);
    dim3 wg((WSZ/4 + 255)/256, 4);
    cvtw_kernel<<<wg, 256>>>(Wq, Wk, Wv, Wo, wf);

    // fused QKV projection (12 n-blocks: 4 per gemm, g = y/4)
    dim3 gq(MROWS / 128, 12);
    gemm_f16<<<gq, 256, GSM_BYTES>>>(xf, wf, bq, bk, bv, pq, pk, pv, 0x3);

    chunk_sums_kernel<<<NBH * NCH, 256, 2 * 128 * 68 * 4>>>();

    int totalPref = NBH * (DD * DD + DD);
    prefix_kernel<<<(totalPref + 255) / 256, 256>>>();

    chunk_attn_kernel<<<NBH * NCH, 256, SMC_FLOATS * 4>>>();

    // output projection (g=0 only, weight index 3)
    dim3 go(MROWS / 128, 4);
    gemm_f16<<<go, 256, GSM_BYTES>>>(af, wf + 3*WSZ, bo, bo, bo, out, out, out, 0x0);
}

// round 12
// speedup vs baseline: 5.8850x; 1.8031x over previous
#include <cuda_runtime.h>
#include <cuda_fp16.h>
#include <math.h>
#include <stdint.h>

#define BB 2
#define TT 4096
#define EE 512
#define HH 8
#define DD 64
#define CHUNK 128
#define NCH (TT/CHUNK)     // 32
#define NBH (BB*HH)        // 16
#define EPSF 1e-6f
#define MROWS (BB*TT)      // 8192
#define WSZ (EE*EE)

// ---------------- scratch (__device__ globals) ---------------------------------
__device__ float g_Mc[NBH*NCH*DD*DD];
__device__ float g_zc[NBH*NCH*DD];
__device__ float g_Mp[NBH*NCH*DD*DD];
__device__ float g_zp[NBH*NCH*DD];

__device__ __half g_xf[MROWS*EE];
__device__ __half g_qf[MROWS*EE];
__device__ __half g_kf[MROWS*EE];
__device__ __half g_vf[MROWS*EE];
__device__ __half g_af[MROWS*EE];
__device__ __half g_wf[4*WSZ];

// ---------------- helpers -------------------------------------------------------
__device__ __forceinline__ uint32_t smem_u32(const void* p) {
    uint32_t a;
    asm("{ .reg .u64 t; cvta.to.shared.u64 t, %1; cvt.u32.u64 %0, t; }"
        : "=r"(a) : "l"(p));
    return a;
}

#define SWZ128(x) ((x) ^ (((x) >> 3) & 0x70))

__device__ __forceinline__ void cp16(uint32_t dst, const void* src) {
    asm volatile("cp.async.cg.shared.global [%0], [%1], 16;" :: "r"(dst), "l"(src));
}
__device__ __forceinline__ void cp_commit() {
    asm volatile("cp.async.commit_group;" ::: "memory");
}
__device__ __forceinline__ void cp_wait0() {
    asm volatile("cp.async.wait_group 0;" ::: "memory");
}

__device__ __forceinline__ void ldsm_x4(uint32_t r[4], uint32_t addr) {
    asm volatile("ldmatrix.sync.aligned.m8n8.x4.shared.b16 {%0,%1,%2,%3}, [%4];"
                 : "=r"(r[0]), "=r"(r[1]), "=r"(r[2]), "=r"(r[3]) : "r"(addr));
}
__device__ __forceinline__ void ldsm_x2(uint32_t r[2], uint32_t addr) {
    asm volatile("ldmatrix.sync.aligned.m8n8.x2.shared.b16 {%0,%1}, [%2];"
                 : "=r"(r[0]), "=r"(r[1]) : "r"(addr));
}
__device__ __forceinline__ void mma_f16(float c[4], const uint32_t a[4], const uint32_t b[2]) {
    asm volatile(
        "mma.sync.aligned.m16n8k16.row.col.f32.f16.f16.f32 "
        "{%0,%1,%2,%3}, {%4,%5,%6,%7}, {%8,%9}, {%0,%1,%2,%3};"
        : "+f"(c[0]), "+f"(c[1]), "+f"(c[2]), "+f"(c[3])
        : "r"(a[0]), "r"(a[1]), "r"(a[2]), "r"(a[3]), "r"(b[0]), "r"(b[1]));
}

// ---------------- convert: fp32 -> fp16 -----------------------------------------
__global__ __launch_bounds__(256) void cvt16_kernel(
    const float* __restrict__ s, __half* __restrict__ d, int n4)
{
    int i = blockIdx.x * 256 + threadIdx.x;
    if (i >= n4) return;
    float4 v = ((const float4*)s)[i];
    __half2* dp = (__half2*)d;
    dp[i*2+0] = __floats2half2_rn(v.x, v.y);
    dp[i*2+1] = __floats2half2_rn(v.z, v.w);
}

__global__ __launch_bounds__(256) void cvtw_kernel(
    const float* __restrict__ w0, const float* __restrict__ w1,
    const float* __restrict__ w2, const float* __restrict__ w3,
    __half* __restrict__ d)
{
    int g = blockIdx.y;
    const float* s = (g == 0) ? w0 : (g == 1) ? w1 : (g == 2) ? w2 : w3;
    int i = blockIdx.x * 256 + threadIdx.x;
    if (i >= WSZ/4) return;
    float4 v = ((const float4*)s)[i];
    __half2* dp = (__half2*)(d + (size_t)g * WSZ);
    dp[i*2+0] = __floats2half2_rn(v.x, v.y);
    dp[i*2+1] = __floats2half2_rn(v.z, v.w);
}

// ---------------- mma.sync fp16 GEMM, cp.async double-buffered ------------------
#define OF_A 0
#define OF_B 16384
#define STAGE_BYTES 32768
#define OF_BIAS (2*STAGE_BYTES)
#define GSM_BYTES (2*STAGE_BYTES + 512 + 256)

template<int F16OUT>
__global__ __launch_bounds__(256, 2) void gemm_f16(
    const __half* __restrict__ Af, const __half* __restrict__ Wf,
    const float* b0, const float* b1, const float* b2,
    void* Y0, void* Y1, void* Y2, int actmask)
{
    extern __shared__ char smem_raw[];
    uint32_t sb0 = smem_u32(smem_raw);
    uint32_t sb  = (sb0 + 127) & ~127u;
    char* smb = smem_raw + (sb - sb0);

    const int tid = threadIdx.x, lid = tid & 31, wid = tid >> 5;
    const int wm = (wid & 1) * 64;
    const int wn = (wid >> 1) * 32;
    const int g  = blockIdx.y >> 2;
    const int m0 = blockIdx.x * 128, n0 = (blockIdx.y & 3) * 128;

    const __half* Bf = Wf + (size_t)g * WSZ;
    const float* bias = (g == 0) ? b0 : (g == 1) ? b1 : b2;
    void* Yv = (g == 0) ? Y0 : (g == 1) ? Y1 : Y2;
    const bool act = (actmask >> g) & 1;

    float* sbias = (float*)(smb + OF_BIAS);
    if (tid < 128) sbias[tid] = bias[n0 + tid];

    float acc[4][4][4];
#pragma unroll
    for (int mi = 0; mi < 4; mi++)
#pragma unroll
        for (int ni = 0; ni < 4; ni++)
#pragma unroll
            for (int kk = 0; kk < 4; kk++) acc[mi][ni][kk] = 0.f;

    const int arow = wm + (lid & 15);
    const int acolb = (lid >> 4) << 3;
    const int brow = wn + (lid & 7);
    const int bcolb = (lid & 8);

    const int lrow = tid >> 3, lj = tid & 7;
#define ISSUE_LOAD(st, k0) do {                                                   \
    uint32_t base = sb + (st) * STAGE_BYTES;                                      \
    _Pragma("unroll")                                                             \
    for (int p = 0; p < 4; p++) {                                                 \
        int row = lrow + p * 32;                                                  \
        uint32_t off = SWZ128((uint32_t)(row * 128 + lj * 16));                   \
        cp16(base + OF_A + off, Af + (size_t)(m0 + row) * EE + (k0) + lj * 8);    \
        cp16(base + OF_B + off, Bf + (size_t)(n0 + row) * EE + (k0) + lj * 8);    \
    }                                                                             \
    cp_commit();                                                                  \
} while (0)

    ISSUE_LOAD(0, 0);
    int cur = 0;
    for (int c = 0; c < 8; c++) {
        cp_wait0();
        __syncthreads();
        if (c < 7) ISSUE_LOAD(cur ^ 1, (c + 1) * 64);

        uint32_t tb = sb + cur * STAGE_BYTES;
#pragma unroll
        for (int ks = 0; ks < 4; ks++) {
            uint32_t ar[4][4], br[4][2];
            int ak = ks * 16 + acolb;
#pragma unroll
            for (int mi = 0; mi < 4; mi++) {
                uint32_t off = SWZ128((uint32_t)((arow + mi * 16) * 128 + ak * 2));
                ldsm_x4(ar[mi], tb + OF_A + off);
            }
            int bk = ks * 16 + bcolb;
#pragma unroll
            for (int ni = 0; ni < 4; ni++) {
                uint32_t off = SWZ128((uint32_t)((brow + ni * 8) * 128 + bk * 2));
                ldsm_x2(br[ni], tb + OF_B + off);
            }
#pragma unroll
            for (int mi = 0; mi < 4; mi++)
#pragma unroll
                for (int ni = 0; ni < 4; ni++)
                    mma_f16(acc[mi][ni], ar[mi], br[ni]);
        }
        cur ^= 1;
    }
#undef ISSUE_LOAD

    const int er = lid >> 2, ec = (lid & 3) * 2;
#pragma unroll
    for (int mi = 0; mi < 4; mi++) {
#pragma unroll
        for (int ni = 0; ni < 4; ni++) {
            int nn = wn + ni * 8 + ec;
            float bb0 = sbias[nn], bb1 = sbias[nn + 1];
            int m1 = m0 + wm + mi * 16 + er;
            float2 v0 = make_float2(acc[mi][ni][0] + bb0, acc[mi][ni][1] + bb1);
            float2 v1 = make_float2(acc[mi][ni][2] + bb0, acc[mi][ni][3] + bb1);
            if (act) {
                v0.x = (v0.x > 0.f) ? (v0.x + 1.f) : expf(v0.x);
                v0.y = (v0.y > 0.f) ? (v0.y + 1.f) : expf(v0.y);
                v1.x = (v1.x > 0.f) ? (v1.x + 1.f) : expf(v1.x);
                v1.y = (v1.y > 0.f) ? (v1.y + 1.f) : expf(v1.y);
            }
            if (F16OUT) {
                __half* Y = (__half*)Yv;
                *(__half2*)&Y[(size_t)m1 * EE + n0 + nn]       = __floats2half2_rn(v0.x, v0.y);
                *(__half2*)&Y[(size_t)(m1 + 8) * EE + n0 + nn] = __floats2half2_rn(v1.x, v1.y);
            } else {
                float* Y = (float*)Yv;
                *(float2*)&Y[(size_t)m1 * EE + n0 + nn] = v0;
                *(float2*)&Y[(size_t)(m1 + 8) * EE + n0 + nn] = v1;
            }
        }
    }
}

// ---------------- Pass A: Mc = K^T V + z via mma --------------------------------
// smem halves: KT [64][136] @0, VT [64][136] @8704. 34816 B total.
__global__ __launch_bounds__(256) void chunk_sums_kernel()
{
    int blk = blockIdx.x;
    int bh = blk / NCH, c = blk % NCH;
    int b = bh / HH, h = bh % HH;

    extern __shared__ __half sh[];
    __half* KT = sh;
    __half* VT = sh + 64 * 136;
    int tid = threadIdx.x;
    size_t base = ((size_t)b * TT + (size_t)c * CHUNK) * EE + h * DD;

    for (int i = tid; i < 128 * 32; i += 256) {
        int e2 = i & 31, t = i >> 5;
        __half2 kv = *(const __half2*)&g_kf[base + (size_t)t * EE + e2 * 2];
        __half2 vv = *(const __half2*)&g_vf[base + (size_t)t * EE + e2 * 2];
        KT[(2*e2) * 136 + t] = __low2half(kv);  KT[(2*e2+1) * 136 + t] = __high2half(kv);
        VT[(2*e2) * 136 + t] = __low2half(vv);  VT[(2*e2+1) * 136 + t] = __high2half(vv);
    }
    __syncthreads();

    uint32_t sb = smem_u32(sh);
    int lid = tid & 31, wid = tid >> 5;
    int wm = (wid & 1) * 32, wn = (wid >> 1) * 16;
    float acc[2][2][4];
#pragma unroll
    for (int mi = 0; mi < 2; mi++)
#pragma unroll
        for (int ni = 0; ni < 2; ni++)
#pragma unroll
            for (int kk = 0; kk < 4; kk++) acc[mi][ni][kk] = 0.f;

    const int arow = lid & 15, acol = (lid >> 4) << 3;
    const int brow = lid & 7,  bcol = lid & 8;

#pragma unroll
    for (int kt = 0; kt < 8; kt++) {
        int k0 = kt * 16;
        uint32_t ar[2][4], br[2][2];
#pragma unroll
        for (int mi = 0; mi < 2; mi++)
            ldsm_x4(ar[mi], sb + ((wm + mi*16 + arow) * 136 + k0 + acol) * 2);
#pragma unroll
        for (int ni = 0; ni < 2; ni++)
            ldsm_x2(br[ni], sb + (64*136 + (wn + ni*8 + brow) * 136 + k0 + bcol) * 2);
#pragma unroll
        for (int mi = 0; mi < 2; mi++)
#pragma unroll
            for (int ni = 0; ni < 2; ni++)
                mma_f16(acc[mi][ni], ar[mi], br[ni]);
    }

    int er = lid >> 2, ec = (lid & 3) * 2;
    float* Mout = g_Mc + (size_t)blk * DD * DD;
#pragma unroll
    for (int mi = 0; mi < 2; mi++)
#pragma unroll
        for (int ni = 0; ni < 2; ni++) {
            int d = wm + mi * 16 + er, e = wn + ni * 8 + ec;
            *(float2*)&Mout[d * DD + e]       = make_float2(acc[mi][ni][0], acc[mi][ni][1]);
            *(float2*)&Mout[(d + 8) * DD + e] = make_float2(acc[mi][ni][2], acc[mi][ni][3]);
        }

    if (tid < DD) {
        float zz = 0.f;
        const __half2* row = (const __half2*)&KT[tid * 136];
#pragma unroll 8
        for (int t2 = 0; t2 < 64; t2++) {
            float2 f = __half22float2(row[t2]);
            zz += f.x + f.y;
        }
        g_zc[(size_t)blk * DD + tid] = zz;
    }
}

// ---------------- Pass B: exclusive prefix over chunks (fp32) -------------------
__global__ void prefix_kernel()
{
    int idx = blockIdx.x * 256 + threadIdx.x;
    const int PER = DD * DD + DD;
    if (idx >= NBH * PER) return;
    int bh = idx / PER;
    int r  = idx % PER;
    if (r < DD * DD) {
        float run = 0.f;
        for (int c = 0; c < NCH; c++) {
            size_t o = (size_t)(bh * NCH + c) * DD * DD + r;
            g_Mp[o] = run;
            run += g_Mc[o];
        }
    } else {
        int d = r - DD * DD;
        float run = 0.f;
        for (int c = 0; c < NCH; c++) {
            size_t o = (size_t)(bh * NCH + c) * DD + d;
            g_zp[o] = run;
            run += g_zc[o];
        }
    }
}

// ---------------- Pass C: tensorized intra-chunk attention ----------------------
// smem (halves): QF[128][72]@0, KF[128][72]@9216, VT[64][136]@18432,
// STH[64][72]@27136, STL[64][72]@31744, A[128][136]@36352 (end 53760 h = 107520 B)
// f32: z[64]@107520B, sdi[128]@107776B.  Total 108288 B.
#define CA_QF 0
#define CA_KF 9216
#define CA_VT 18432
#define CA_STH 27136
#define CA_STL 31744
#define CA_A  36352
#define CA_ZB 107520
#define CA_DIB 107776
#define CA_BYTES 108544

__global__ __launch_bounds__(256, 1) void chunk_attn_kernel()
{
    int blk = blockIdx.x;
    int bh = blk / NCH, c = blk % NCH;
    int b = bh / HH, h = bh % HH;

    extern __shared__ char smc[];
    __half* sh = (__half*)smc;
    float* zf  = (float*)(smc + CA_ZB);
    float* sdi = (float*)(smc + CA_DIB);
    uint32_t sb = smem_u32(smc);

    int tid = threadIdx.x, lid = tid & 31, wid = tid >> 5;
    size_t base = ((size_t)b * TT + (size_t)c * CHUNK) * EE + h * DD;
    const float* Mp = g_Mp + (size_t)blk * DD * DD;
    const float* zp = g_zp + (size_t)blk * DD;

    // q,k row-major fp16
    for (int i = tid; i < 128 * 8; i += 256) {
        int row = i >> 3, j = i & 7;
        *(uint4*)&sh[CA_QF + row * 72 + j * 8] =
            *(const uint4*)&g_qf[base + (size_t)row * EE + j * 8];
        *(uint4*)&sh[CA_KF + row * 72 + j * 8] =
            *(const uint4*)&g_kf[base + (size_t)row * EE + j * 8];
    }
    // V transposed
    for (int i = tid; i < 128 * 32; i += 256) {
        int e2 = i & 31, t = i >> 5;
        __half2 vv = *(const __half2*)&g_vf[base + (size_t)t * EE + e2 * 2];
        sh[CA_VT + (2*e2) * 136 + t] = __low2half(vv);
        sh[CA_VT + (2*e2+1) * 136 + t] = __high2half(vv);
    }
    // S^T hi/lo
    for (int i = tid; i < 64 * 16; i += 256) {
        int d = i >> 4, e4 = (i & 15) * 4;
        float4 s4 = *(const float4*)&Mp[d * DD + e4];
        float fs[4] = {s4.x, s4.y, s4.z, s4.w};
#pragma unroll
        for (int j = 0; j < 4; j++) {
            __half hi = __float2half(fs[j]);
            sh[CA_STH + (e4 + j) * 72 + d] = hi;
            sh[CA_STL + (e4 + j) * 72 + d] = __float2half(fs[j] - __half2float(hi));
        }
    }
    if (tid < DD) zf[tid] = zp[tid];
    __syncthreads();

    // ---- phase 1: A = Q K^T (causal-masked), fp16 into smem ----
    {
        int wm = (wid & 1) * 64, wn = (wid >> 1) * 32;
        const int arow = lid & 15, acol = (lid >> 4) << 3;
        const int brow = lid & 7,  bcol = lid & 8;
        float acc[4][4][4];
#pragma unroll
        for (int mi = 0; mi < 4; mi++)
#pragma unroll
            for (int ni = 0; ni < 4; ni++)
#pragma unroll
                for (int kk = 0; kk < 4; kk++) acc[mi][ni][kk] = 0.f;

#pragma unroll
        for (int kt = 0; kt < 4; kt++) {
            int k0 = kt * 16;
            uint32_t ar[4][4], br[4][2];
#pragma unroll
            for (int mi = 0; mi < 4; mi++)
                ldsm_x4(ar[mi], sb + (CA_QF + (wm + mi*16 + arow) * 72 + k0 + acol) * 2);
#pragma unroll
            for (int ni = 0; ni < 4; ni++)
                ldsm_x2(br[ni], sb + (CA_KF + (wn + ni*8 + brow) * 72 + k0 + bcol) * 2);
#pragma unroll
            for (int mi = 0; mi < 4; mi++)
#pragma unroll
                for (int ni = 0; ni < 4; ni++)
                    mma_f16(acc[mi][ni], ar[mi], br[ni]);
        }

        int er = lid >> 2, ec = (lid & 3) * 2;
#pragma unroll
        for (int mi = 0; mi < 4; mi++)
#pragma unroll
            for (int ni = 0; ni < 4; ni++) {
                int t = wm + mi * 16 + er, s = wn + ni * 8 + ec;
                float c0 = (s     <= t) ? acc[mi][ni][0] : 0.f;
                float c1 = (s + 1 <= t) ? acc[mi][ni][1] : 0.f;
                int t2 = t + 8;
                float c2 = (s     <= t2) ? acc[mi][ni][2] : 0.f;
                float c3 = (s + 1 <= t2) ? acc[mi][ni][3] : 0.f;
                *(__half2*)&sh[CA_A + t  * 136 + s] = __floats2half2_rn(c0, c1);
                *(__half2*)&sh[CA_A + t2 * 136 + s] = __floats2half2_rn(c2, c3);
            }
    }
    __syncthreads();

    // ---- denominators ----
    if (tid < CHUNK) {
        int t = tid;
        float den = EPSF;
        const __half2* qr = (const __half2*)&sh[CA_QF + t * 72];
#pragma unroll 8
        for (int d2 = 0; d2 < 32; d2++) {
            float2 q = __half22float2(qr[d2]);
            den += q.x * zf[2*d2] + q.y * zf[2*d2 + 1];
        }
        const __half2* ar = (const __half2*)&sh[CA_A + t * 136];
#pragma unroll 8
        for (int s2 = 0; s2 < 64; s2++) {
            float2 a = __half22float2(ar[s2]);
            den += a.x + a.y;
        }
        sdi[t] = 1.f / den;
    }
    __syncthreads();

    // ---- phase 2: out = (A V + Q Sh + Q Sl) * inv_den -> g_af fp16 ----
    {
        int wm = (wid & 1) * 64, wn = (wid >> 1) * 16;
        const int arow = lid & 15, acol = (lid >> 4) << 3;
        const int brow = lid & 7,  bcol = lid & 8;
        float acc[4][2][4];
#pragma unroll
        for (int mi = 0; mi < 4; mi++)
#pragma unroll
            for (int ni = 0; ni < 2; ni++)
#pragma unroll
                for (int kk = 0; kk < 4; kk++) acc[mi][ni][kk] = 0.f;

        // A V  (k = s, 8 tiles)
#pragma unroll
        for (int kt = 0; kt < 8; kt++) {
            int k0 = kt * 16;
            uint32_t ar[4][4], br[2][2];
#pragma unroll
            for (int mi = 0; mi < 4; mi++)
                ldsm_x4(ar[mi], sb + (CA_A + (wm + mi*16 + arow) * 136 + k0 + acol) * 2);
#pragma unroll
            for (int ni = 0; ni < 2; ni++)
                ldsm_x2(br[ni], sb + (CA_VT + (wn + ni*8 + brow) * 136 + k0 + bcol) * 2);
#pragma unroll
            for (int mi = 0; mi < 4; mi++)
#pragma unroll
                for (int ni = 0; ni < 2; ni++)
                    mma_f16(acc[mi][ni], ar[mi], br[ni]);
        }
        // Q S_hi + Q S_lo  (k = d, 4 tiles each)
#pragma unroll
        for (int pass = 0; pass < 2; pass++) {
            int stoff = pass ? CA_STL : CA_STH;
#pragma unroll
            for (int kt = 0; kt < 4; kt++) {
                int k0 = kt * 16;
                uint32_t ar[4][4], br[2][2];
#pragma unroll
                for (int mi = 0; mi < 4; mi++)
                    ldsm_x4(ar[mi], sb + (CA_QF + (wm + mi*16 + arow) * 72 + k0 + acol) * 2);
#pragma unroll
                for (int ni = 0; ni < 2; ni++)
                    ldsm_x2(br[ni], sb + (stoff + (wn + ni*8 + brow) * 72 + k0 + bcol) * 2);
#pragma unroll
                for (int mi = 0; mi < 4; mi++)
#pragma unroll
                    for (int ni = 0; ni < 2; ni++)
                        mma_f16(acc[mi][ni], ar[mi], br[ni]);
            }
        }

        int er = lid >> 2, ec = (lid & 3) * 2;
#pragma unroll
        for (int mi = 0; mi < 4; mi++)
#pragma unroll
            for (int ni = 0; ni < 2; ni++) {
                int t = wm + mi * 16 + er, e = wn + ni * 8 + ec;
                float i0 = sdi[t], i1 = sdi[t + 8];
                *(__half2*)&g_af[base + (size_t)t * EE + e] =
                    __floats2half2_rn(acc[mi][ni][0] * i0, acc[mi][ni][1] * i0);
                *(__half2*)&g_af[base + (size_t)(t + 8) * EE + e] =
                    __floats2half2_rn(acc[mi][ni][2] * i1, acc[mi][ni][3] * i1);
            }
    }
}

// ---------------- host ----------------------------------------------------------
extern "C" void kernel_launch(void* const* d_in, const int* in_sizes, int n_in,
                              void* d_out, int out_size)
{
    const float* x  = (const float*)d_in[0];
    const float* Wq = (const float*)d_in[1];
    const float* bq = (const float*)d_in[2];
    const float* Wk = (const float*)d_in[3];
    const float* bk = (const float*)d_in[4];
    const float* Wv = (const float*)d_in[5];
    const float* bv = (const float*)d_in[6];
    const float* Wo = (const float*)d_in[7];
    const float* bo = (const float*)d_in[8];
    float* out = (float*)d_out;

    __half *xf, *qf, *kf, *vf, *af, *wf;
    cudaGetSymbolAddress((void**)&xf, g_xf);
    cudaGetSymbolAddress((void**)&qf, g_qf);
    cudaGetSymbolAddress((void**)&kf, g_kf);
    cudaGetSymbolAddress((void**)&vf, g_vf);
    cudaGetSymbolAddress((void**)&af, g_af);
    cudaGetSymbolAddress((void**)&wf, g_wf);

    cudaFuncSetAttribute(gemm_f16<0>, cudaFuncAttributeMaxDynamicSharedMemorySize, GSM_BYTES);
    cudaFuncSetAttribute(gemm_f16<1>, cudaFuncAttributeMaxDynamicSharedMemorySize, GSM_BYTES);
    cudaFuncSetAttribute(chunk_sums_kernel,
                         cudaFuncAttributeMaxDynamicSharedMemorySize, 2 * 64 * 136 * 2);
    cudaFuncSetAttribute(chunk_attn_kernel,
                         cudaFuncAttributeMaxDynamicSharedMemorySize, CA_BYTES);

    cvt16_kernel<<<(MROWS*EE/4 + 255)/256, 256>>>(x, xf, MROWS*EE/4);
    dim3 wg((WSZ/4 + 255)/256, 4);
    cvtw_kernel<<<wg, 256>>>(Wq, Wk, Wv, Wo, wf);

    // fused QKV projection -> fp16 q/k/v with elu+1 on q,k
    dim3 gq(MROWS / 128, 12);
    gemm_f16<1><<<gq, 256, GSM_BYTES>>>(xf, wf, bq, bk, bv, qf, kf, vf, 0x3);

    chunk_sums_kernel<<<NBH * NCH, 256, 2 * 64 * 136 * 2>>>();

    int totalPref = NBH * (DD * DD + DD);
    prefix_kernel<<<(totalPref + 255) / 256, 256>>>();

    chunk_attn_kernel<<<NBH * NCH, 256, CA_BYTES>>>();

    // output projection -> fp32 d_out
    dim3 go(MROWS / 128, 4);
    gemm_f16<0><<<go, 256, GSM_BYTES>>>(af, wf + 3*WSZ, bo, bo, bo, out, out, out, 0x0);
}